// round 1
// baseline (speedup 1.0000x reference)
#include <cuda_runtime.h>

#define DW 8
#define FFN_N 1024
#define BLOCK 256

__global__ __launch_bounds__(BLOCK, 3)
void qtb_kernel(const float* __restrict__ x,
                const float* __restrict__ ln1_g, const float* __restrict__ ln1_b,
                const float* __restrict__ ln2_g, const float* __restrict__ ln2_b,
                const float* __restrict__ rp, const float* __restrict__ theta,
                const float* __restrict__ w1, const float* __restrict__ b1,
                const float* __restrict__ w2, const float* __restrict__ b2,
                float* __restrict__ out, int ntok)
{
    // sw2[j*8 + w] = w2[w*1024 + j]  (transposed so a unit's 8 output weights are contiguous)
    __shared__ float sw2[FFN_N * DW];
    __shared__ float sb1[FFN_N];

    const int tid = threadIdx.x;
    for (int i = tid; i < FFN_N * DW; i += BLOCK) {
        int w = i >> 10;          // 0..7
        int j = i & (FFN_N - 1);  // 0..1023
        sw2[j * DW + w] = w2[i];  // coalesced global read, scattered smem write
    }
    for (int i = tid; i < FFN_N; i += BLOCK) sb1[i] = b1[i];
    __syncthreads();

    const int tok = blockIdx.x * BLOCK + tid;
    if (tok >= ntok) return;

    // ---- load token (8 contiguous floats) ----
    const float4 xa = *(const float4*)(x + (size_t)tok * DW);
    const float4 xb = *(const float4*)(x + (size_t)tok * DW + 4);
    float xv[8] = {xa.x, xa.y, xa.z, xa.w, xb.x, xb.y, xb.z, xb.w};

    const float p0 = __ldg(rp + 0);
    const float p1 = __ldg(rp + 1);
    const float p3 = __ldg(rp + 3);
    const float p4 = __ldg(rp + 4);

    // ---- analytic quantum layer: attn_out = <Z_w> ----
    float a[8];
    {
        float c0 = cosf(xv[0] + p0);
        float c2 = cosf(xv[2]);
        a[0] = c0;
        a[1] = c0 * cosf(p1) * cosf(xv[1]);
        a[2] = c2;
        a[3] = c2 * cosf(xv[3]);
        a[4] = cosf(xv[4] + p3);
        a[5] = cosf(p4) * cosf(xv[5]);
        a[6] = cosf(xv[6]);
        a[7] = cosf(xv[7]);
    }

    // ---- h = LN1(x + attn_out) ----
    float h[8];
    {
        float y[8], mu = 0.f;
        #pragma unroll
        for (int w = 0; w < 8; w++) { y[w] = xv[w] + a[w]; mu += y[w]; }
        mu *= 0.125f;
        float var = 0.f;
        #pragma unroll
        for (int w = 0; w < 8; w++) { float d = y[w] - mu; var += d * d; }
        var *= 0.125f;
        float rs = rsqrtf(var + 1e-5f);
        #pragma unroll
        for (int w = 0; w < 8; w++)
            h[w] = (y[w] - mu) * rs * __ldg(ln1_g + w) + __ldg(ln1_b + w);
    }

    // ---- q = cos(theta_w) * cos(a_w)  (second circuit collapsed) ----
    float q[8];
    #pragma unroll
    for (int w = 0; w < 8; w++) q[w] = cosf(__ldg(theta + w)) * cosf(a[w]);

    // ---- FFN: relu(q @ W1^T + b1) @ W2^T ----
    // All lanes of a warp walk the same unit j: W1 row via broadcast L1 LDG,
    // W2 column via broadcast smem LDS. 17 FMA-pipe ops per unit dominates.
    float acc[8] = {0.f, 0.f, 0.f, 0.f, 0.f, 0.f, 0.f, 0.f};
    const float4* w1v = (const float4*)w1;
    #pragma unroll 2
    for (int j = 0; j < FFN_N; j++) {
        float4 wa = __ldg(w1v + 2 * j);
        float4 wb = __ldg(w1v + 2 * j + 1);
        float t0 = fmaf(q[0], wa.x, sb1[j]);
        t0 = fmaf(q[1], wa.y, t0);
        t0 = fmaf(q[2], wa.z, t0);
        t0 = fmaf(q[3], wa.w, t0);
        float t1 = q[4] * wb.x;
        t1 = fmaf(q[5], wb.y, t1);
        t1 = fmaf(q[6], wb.z, t1);
        t1 = fmaf(q[7], wb.w, t1);
        float hh = fmaxf(t0 + t1, 0.f);
        float4 va = *(const float4*)(sw2 + j * DW);
        float4 vb = *(const float4*)(sw2 + j * DW + 4);
        acc[0] = fmaf(hh, va.x, acc[0]);
        acc[1] = fmaf(hh, va.y, acc[1]);
        acc[2] = fmaf(hh, va.z, acc[2]);
        acc[3] = fmaf(hh, va.w, acc[3]);
        acc[4] = fmaf(hh, vb.x, acc[4]);
        acc[5] = fmaf(hh, vb.y, acc[5]);
        acc[6] = fmaf(hh, vb.z, acc[6]);
        acc[7] = fmaf(hh, vb.w, acc[7]);
    }

    // ---- out = LN2(h + ffn_out) ----
    float z[8], mu = 0.f;
    #pragma unroll
    for (int w = 0; w < 8; w++) { z[w] = h[w] + acc[w] + __ldg(b2 + w); mu += z[w]; }
    mu *= 0.125f;
    float var = 0.f;
    #pragma unroll
    for (int w = 0; w < 8; w++) { float d = z[w] - mu; var += d * d; }
    var *= 0.125f;
    float rs = rsqrtf(var + 1e-5f);
    float o[8];
    #pragma unroll
    for (int w = 0; w < 8; w++)
        o[w] = (z[w] - mu) * rs * __ldg(ln2_g + w) + __ldg(ln2_b + w);

    *(float4*)(out + (size_t)tok * DW)     = make_float4(o[0], o[1], o[2], o[3]);
    *(float4*)(out + (size_t)tok * DW + 4) = make_float4(o[4], o[5], o[6], o[7]);
}

extern "C" void kernel_launch(void* const* d_in, const int* in_sizes, int n_in,
                              void* d_out, int out_size) {
    const float* x     = (const float*)d_in[0];
    const float* ln1_g = (const float*)d_in[1];
    const float* ln1_b = (const float*)d_in[2];
    const float* ln2_g = (const float*)d_in[3];
    const float* ln2_b = (const float*)d_in[4];
    const float* rp    = (const float*)d_in[5];
    const float* theta = (const float*)d_in[6];
    const float* w1    = (const float*)d_in[7];
    const float* b1    = (const float*)d_in[8];
    const float* w2    = (const float*)d_in[9];
    const float* b2    = (const float*)d_in[10];
    float* out = (float*)d_out;

    int ntok = in_sizes[0] / DW;  // 131072
    int blocks = (ntok + BLOCK - 1) / BLOCK;
    qtb_kernel<<<blocks, BLOCK>>>(x, ln1_g, ln1_b, ln2_g, ln2_b, rp, theta,
                                  w1, b1, w2, b2, out, ntok);
}

// round 2
// speedup vs baseline: 1.8846x; 1.8846x over previous
#include <cuda_runtime.h>

#define NTOK   (64 * 2048)     // 131072 tokens
#define DW     8
#define FFN_N  1024
#define SPLIT  4
#define JCHUNK (FFN_N / SPLIT) // 256
#define TPT    8               // tokens per thread in FFN kernel
#define FBLK   128             // FFN kernel block size

typedef unsigned long long ull;

// Static scratch (no allocations allowed)
__device__ float g_h[NTOK * DW];                 // 4 MB : LN1 output
__device__ float g_q[NTOK * DW];                 // 4 MB : FFN input
__device__ float g_part[(size_t)SPLIT * NTOK * DW]; // 16 MB : partial FFN2 sums

// ---- packed f32x2 helpers ----
__device__ __forceinline__ ull pk2(float a, float b) {
    ull r; asm("mov.b64 %0, {%1, %2};" : "=l"(r) : "f"(a), "f"(b)); return r;
}
__device__ __forceinline__ void upk(ull v, float& a, float& b) {
    asm("mov.b64 {%0, %1}, %2;" : "=f"(a), "=f"(b) : "l"(v));
}
__device__ __forceinline__ ull ffma2(ull a, ull b, ull c) {
    ull d; asm("fma.rn.f32x2 %0, %1, %2, %3;" : "=l"(d) : "l"(a), "l"(b), "l"(c)); return d;
}

// ============================================================
// Kernel 1: analytic quantum layer + LN1  ->  g_h, g_q
// ============================================================
__global__ __launch_bounds__(256)
void k_prologue(const float* __restrict__ x,
                const float* __restrict__ ln1_g, const float* __restrict__ ln1_b,
                const float* __restrict__ rp,   const float* __restrict__ theta)
{
    const int tok = blockIdx.x * 256 + threadIdx.x;
    if (tok >= NTOK) return;

    const float4 xa = *(const float4*)(x + (size_t)tok * DW);
    const float4 xb = *(const float4*)(x + (size_t)tok * DW + 4);
    float xv[8] = {xa.x, xa.y, xa.z, xa.w, xb.x, xb.y, xb.z, xb.w};

    const float p0 = __ldg(rp + 0), p1 = __ldg(rp + 1);
    const float p3 = __ldg(rp + 3), p4 = __ldg(rp + 4);

    float a[8];
    {
        float c0 = cosf(xv[0] + p0);
        float c2 = cosf(xv[2]);
        a[0] = c0;
        a[1] = c0 * cosf(p1) * cosf(xv[1]);
        a[2] = c2;
        a[3] = c2 * cosf(xv[3]);
        a[4] = cosf(xv[4] + p3);
        a[5] = cosf(p4) * cosf(xv[5]);
        a[6] = cosf(xv[6]);
        a[7] = cosf(xv[7]);
    }

    // h = LN1(x + a)
    float h[8];
    {
        float y[8], mu = 0.f;
        #pragma unroll
        for (int w = 0; w < 8; w++) { y[w] = xv[w] + a[w]; mu += y[w]; }
        mu *= 0.125f;
        float var = 0.f;
        #pragma unroll
        for (int w = 0; w < 8; w++) { float d = y[w] - mu; var += d * d; }
        var *= 0.125f;
        float rs = rsqrtf(var + 1e-5f);
        #pragma unroll
        for (int w = 0; w < 8; w++)
            h[w] = (y[w] - mu) * rs * __ldg(ln1_g + w) + __ldg(ln1_b + w);
    }

    float q[8];
    #pragma unroll
    for (int w = 0; w < 8; w++) q[w] = cosf(__ldg(theta + w)) * cosf(a[w]);

    *(float4*)(g_h + (size_t)tok * DW)     = make_float4(h[0], h[1], h[2], h[3]);
    *(float4*)(g_h + (size_t)tok * DW + 4) = make_float4(h[4], h[5], h[6], h[7]);
    *(float4*)(g_q + (size_t)tok * DW)     = make_float4(q[0], q[1], q[2], q[3]);
    *(float4*)(g_q + (size_t)tok * DW + 4) = make_float4(q[4], q[5], q[6], q[7]);
}

// ============================================================
// Kernel 2: split-j FFN with packed f32x2, T=8 tokens/thread
//   block = (group, chunk); partial acc -> g_part[chunk]
// ============================================================
__global__ __launch_bounds__(FBLK, 2)
void k_ffn(const float* __restrict__ w1, const float* __restrict__ b1,
           const float* __restrict__ w2)
{
    __shared__ float sw2[JCHUNK * DW];  // sw2[jj*8+w] = w2[w*1024 + j0+jj]
    __shared__ float sb1[JCHUNK];

    const int chunk = blockIdx.x & (SPLIT - 1);
    const int grp   = blockIdx.x >> 2;
    const int j0    = chunk * JCHUNK;
    const int tid   = threadIdx.x;

    for (int i = tid; i < JCHUNK * DW; i += FBLK) {
        int jj = i & (JCHUNK - 1);
        int w  = i >> 8;  // JCHUNK = 256
        sw2[jj * DW + w] = w2[w * FFN_N + j0 + jj];
    }
    for (int i = tid; i < JCHUNK; i += FBLK) sb1[i] = b1[j0 + i];
    __syncthreads();

    const int tok0 = grp * (FBLK * TPT) + tid * TPT;

    // Load q for 8 consecutive tokens, pack token-pairs: qp[p][w] = {q_{2p}[w], q_{2p+1}[w]}
    float qv[TPT][8];
    #pragma unroll
    for (int t = 0; t < TPT; t++) {
        const float4 qa = __ldg((const float4*)(g_q + (size_t)(tok0 + t) * DW));
        const float4 qb = __ldg((const float4*)(g_q + (size_t)(tok0 + t) * DW + 4));
        qv[t][0]=qa.x; qv[t][1]=qa.y; qv[t][2]=qa.z; qv[t][3]=qa.w;
        qv[t][4]=qb.x; qv[t][5]=qb.y; qv[t][6]=qb.z; qv[t][7]=qb.w;
    }
    ull qp[TPT/2][8];
    #pragma unroll
    for (int p = 0; p < TPT/2; p++)
        #pragma unroll
        for (int w = 0; w < 8; w++)
            qp[p][w] = pk2(qv[2*p][w], qv[2*p+1][w]);

    ull acc[TPT/2][8];
    #pragma unroll
    for (int p = 0; p < TPT/2; p++)
        #pragma unroll
        for (int w = 0; w < 8; w++) acc[p][w] = 0ull;

    const float4* w1v = (const float4*)(w1 + (size_t)j0 * DW);

    #pragma unroll 2
    for (int j = 0; j < JCHUNK; j++) {
        const float4 wa = __ldg(w1v + 2 * j);
        const float4 wb = __ldg(w1v + 2 * j + 1);
        const float  bj = sb1[j];
        const float4 va = *(const float4*)(sw2 + j * DW);
        const float4 vb = *(const float4*)(sw2 + j * DW + 4);

        ull w1p[8] = { pk2(wa.x,wa.x), pk2(wa.y,wa.y), pk2(wa.z,wa.z), pk2(wa.w,wa.w),
                       pk2(wb.x,wb.x), pk2(wb.y,wb.y), pk2(wb.z,wb.z), pk2(wb.w,wb.w) };
        ull w2p[8] = { pk2(va.x,va.x), pk2(va.y,va.y), pk2(va.z,va.z), pk2(va.w,va.w),
                       pk2(vb.x,vb.x), pk2(vb.y,vb.y), pk2(vb.z,vb.z), pk2(vb.w,vb.w) };
        const ull bp = pk2(bj, bj);

        #pragma unroll
        for (int p = 0; p < TPT/2; p++) {
            ull t = bp;
            #pragma unroll
            for (int w = 0; w < 8; w++) t = ffma2(qp[p][w], w1p[w], t);
            float h0, h1;
            upk(t, h0, h1);
            h0 = fmaxf(h0, 0.f);
            h1 = fmaxf(h1, 0.f);
            const ull hp = pk2(h0, h1);
            #pragma unroll
            for (int w = 0; w < 8; w++) acc[p][w] = ffma2(hp, w2p[w], acc[p][w]);
        }
    }

    // Store partial sums: two tokens per pair
    float* base = g_part + (size_t)chunk * NTOK * DW;
    #pragma unroll
    for (int p = 0; p < TPT/2; p++) {
        float a0[8], a1[8];
        #pragma unroll
        for (int w = 0; w < 8; w++) upk(acc[p][w], a0[w], a1[w]);
        float* o0 = base + (size_t)(tok0 + 2*p) * DW;
        float* o1 = base + (size_t)(tok0 + 2*p + 1) * DW;
        *(float4*)(o0)     = make_float4(a0[0], a0[1], a0[2], a0[3]);
        *(float4*)(o0 + 4) = make_float4(a0[4], a0[5], a0[6], a0[7]);
        *(float4*)(o1)     = make_float4(a1[0], a1[1], a1[2], a1[3]);
        *(float4*)(o1 + 4) = make_float4(a1[4], a1[5], a1[6], a1[7]);
    }
}

// ============================================================
// Kernel 3: reduce partials + LN2 -> out
// ============================================================
__global__ __launch_bounds__(256)
void k_epilogue(const float* __restrict__ ln2_g, const float* __restrict__ ln2_b,
                const float* __restrict__ b2, float* __restrict__ out)
{
    const int tok = blockIdx.x * 256 + threadIdx.x;
    if (tok >= NTOK) return;

    float z[8];
    {
        const float4 ha = *(const float4*)(g_h + (size_t)tok * DW);
        const float4 hb = *(const float4*)(g_h + (size_t)tok * DW + 4);
        z[0]=ha.x; z[1]=ha.y; z[2]=ha.z; z[3]=ha.w;
        z[4]=hb.x; z[5]=hb.y; z[6]=hb.z; z[7]=hb.w;
    }
    #pragma unroll
    for (int c = 0; c < SPLIT; c++) {
        const float* p = g_part + (size_t)c * NTOK * DW + (size_t)tok * DW;
        const float4 pa = *(const float4*)(p);
        const float4 pb = *(const float4*)(p + 4);
        z[0]+=pa.x; z[1]+=pa.y; z[2]+=pa.z; z[3]+=pa.w;
        z[4]+=pb.x; z[5]+=pb.y; z[6]+=pb.z; z[7]+=pb.w;
    }
    float mu = 0.f;
    #pragma unroll
    for (int w = 0; w < 8; w++) { z[w] += __ldg(b2 + w); mu += z[w]; }
    mu *= 0.125f;
    float var = 0.f;
    #pragma unroll
    for (int w = 0; w < 8; w++) { float d = z[w] - mu; var += d * d; }
    var *= 0.125f;
    const float rs = rsqrtf(var + 1e-5f);
    float o[8];
    #pragma unroll
    for (int w = 0; w < 8; w++)
        o[w] = (z[w] - mu) * rs * __ldg(ln2_g + w) + __ldg(ln2_b + w);

    *(float4*)(out + (size_t)tok * DW)     = make_float4(o[0], o[1], o[2], o[3]);
    *(float4*)(out + (size_t)tok * DW + 4) = make_float4(o[4], o[5], o[6], o[7]);
}

// ============================================================
extern "C" void kernel_launch(void* const* d_in, const int* in_sizes, int n_in,
                              void* d_out, int out_size) {
    const float* x     = (const float*)d_in[0];
    const float* ln1_g = (const float*)d_in[1];
    const float* ln1_b = (const float*)d_in[2];
    const float* ln2_g = (const float*)d_in[3];
    const float* ln2_b = (const float*)d_in[4];
    const float* rp    = (const float*)d_in[5];
    const float* theta = (const float*)d_in[6];
    const float* w1    = (const float*)d_in[7];
    const float* b1    = (const float*)d_in[8];
    const float* w2    = (const float*)d_in[9];
    const float* b2    = (const float*)d_in[10];
    float* out = (float*)d_out;

    k_prologue<<<NTOK / 256, 256>>>(x, ln1_g, ln1_b, rp, theta);

    const int groups = NTOK / (FBLK * TPT);  // 128
    k_ffn<<<groups * SPLIT, FBLK>>>(w1, b1, w2);

    k_epilogue<<<NTOK / 256, 256>>>(ln2_g, ln2_b, b2, out);
}

// round 3
// speedup vs baseline: 2.5127x; 1.3332x over previous
#include <cuda_runtime.h>

#define NTOK   131072
#define DW     8
#define FFN_N  1024
#define SPLIT  8
#define JCHUNK (FFN_N / SPLIT)   // 128
#define JP     (JCHUNK / 2)      // 64 j-pairs
#define FBLK   256
#define TPB    (FBLK * 2)        // 512 tokens per block (2 per thread)

typedef unsigned long long ull;

// Static scratch (no allocations allowed)
__device__ float g_h[NTOK * DW];                      // 4 MB : LN1 output
__device__ float g_part[(size_t)SPLIT * NTOK * DW];   // 32 MB : partial FFN2 sums

// ---- packed f32x2 helpers ----
__device__ __forceinline__ ull pk2(float a, float b) {
    ull r; asm("mov.b64 %0, {%1, %2};" : "=l"(r) : "f"(a), "f"(b)); return r;
}
__device__ __forceinline__ void upk(ull v, float& a, float& b) {
    asm("mov.b64 {%0, %1}, %2;" : "=f"(a), "=f"(b) : "l"(v));
}
__device__ __forceinline__ ull ffma2(ull a, ull b, ull c) {
    ull d; asm("fma.rn.f32x2 %0, %1, %2, %3;" : "=l"(d) : "l"(a), "l"(b), "l"(c)); return d;
}

// ============================================================
// Fused kernel: quantum layer (analytic) + LN1 (chunk 0 only)
// + split-j FFN with j-pair packed f32x2
// block = (grp, chunk): tokens [grp*512, grp*512+512), j in [chunk*128, ...)
// ============================================================
__global__ __launch_bounds__(FBLK, 2)
void k_ffn(const float* __restrict__ x,
           const float* __restrict__ ln1_g, const float* __restrict__ ln1_b,
           const float* __restrict__ rp,    const float* __restrict__ theta,
           const float* __restrict__ w1,    const float* __restrict__ b1,
           const float* __restrict__ w2)
{
    // sw1p[jp*16 + 2w + par] = w1[(j0 + 2jp + par)][w]  (j-pair interleaved)
    __shared__ __align__(16) float sw1p[JCHUNK * DW];
    // sw2[jj*8 + w] = w2[w][j0+jj]  (unit-j column contiguous)
    __shared__ __align__(16) float sw2[JCHUNK * DW];
    __shared__ __align__(8)  float sb1[JCHUNK];

    const int bid   = blockIdx.x;
    const int chunk = bid & (SPLIT - 1);
    const int grp   = bid >> 3;
    const int j0    = chunk * JCHUNK;
    const int tid   = threadIdx.x;

    for (int i = tid; i < JCHUNK * DW; i += FBLK) {
        int jj = i >> 3, w = i & 7;
        sw1p[(jj >> 1) * 16 + 2 * w + (jj & 1)] = w1[(size_t)(j0 + jj) * DW + w];
    }
    for (int i = tid; i < JCHUNK * DW; i += FBLK) {
        int w = i >> 7, jj = i & (JCHUNK - 1);
        sw2[jj * DW + w] = w2[w * FFN_N + j0 + jj];
    }
    for (int i = tid; i < JCHUNK; i += FBLK) sb1[i] = b1[j0 + i];
    __syncthreads();

    const int tokA = grp * TPB + tid;       // token 0 of this thread
    // token 1 is tokA + FBLK (coalesced loads/stores)

    const float p0 = __ldg(rp + 0), p1 = __ldg(rp + 1);
    const float p3 = __ldg(rp + 3), p4 = __ldg(rp + 4);
    float ct[8];
    #pragma unroll
    for (int w = 0; w < 8; w++) ct[w] = __cosf(__ldg(theta + w));

    ull qd[2][8];     // duplicated q, packed {q,q}
    #pragma unroll
    for (int t = 0; t < 2; t++) {
        const int tok = tokA + t * FBLK;
        const float4 xa = __ldg((const float4*)(x + (size_t)tok * DW));
        const float4 xb = __ldg((const float4*)(x + (size_t)tok * DW + 4));
        float xv[8] = {xa.x, xa.y, xa.z, xa.w, xb.x, xb.y, xb.z, xb.w};

        float a[8];
        {
            float c0 = __cosf(xv[0] + p0);
            float c2 = __cosf(xv[2]);
            a[0] = c0;
            a[1] = c0 * __cosf(p1) * __cosf(xv[1]);
            a[2] = c2;
            a[3] = c2 * __cosf(xv[3]);
            a[4] = __cosf(xv[4] + p3);
            a[5] = __cosf(p4) * __cosf(xv[5]);
            a[6] = __cosf(xv[6]);
            a[7] = __cosf(xv[7]);
        }

        if (chunk == 0) {   // h = LN1(x + a), written once
            float y[8], mu = 0.f;
            #pragma unroll
            for (int w = 0; w < 8; w++) { y[w] = xv[w] + a[w]; mu += y[w]; }
            mu *= 0.125f;
            float var = 0.f;
            #pragma unroll
            for (int w = 0; w < 8; w++) { float d = y[w] - mu; var += d * d; }
            var *= 0.125f;
            float rs = rsqrtf(var + 1e-5f);
            float h[8];
            #pragma unroll
            for (int w = 0; w < 8; w++)
                h[w] = (y[w] - mu) * rs * __ldg(ln1_g + w) + __ldg(ln1_b + w);
            *(float4*)(g_h + (size_t)tok * DW)     = make_float4(h[0], h[1], h[2], h[3]);
            *(float4*)(g_h + (size_t)tok * DW + 4) = make_float4(h[4], h[5], h[6], h[7]);
        }

        #pragma unroll
        for (int w = 0; w < 8; w++) {
            float qw = ct[w] * __cosf(a[w]);
            qd[t][w] = pk2(qw, qw);
        }
    }

    ull acc[2][4];   // per token, wire-pairs {2wp, 2wp+1}
    #pragma unroll
    for (int t = 0; t < 2; t++)
        #pragma unroll
        for (int wp = 0; wp < 4; wp++) acc[t][wp] = 0ull;

    #pragma unroll 2
    for (int jp = 0; jp < JP; jp++) {
        const ulonglong2* wv = (const ulonglong2*)(sw1p + jp * 16);
        const ulonglong2 u01 = wv[0], u23 = wv[1], u45 = wv[2], u67 = wv[3];
        const ull bp = *(const ull*)(sb1 + jp * 2);
        const ulonglong2* vv = (const ulonglong2*)(sw2 + (size_t)(2 * jp) * DW);
        const ulonglong2 vj0a = vv[0], vj0b = vv[1];   // w2 col of j   (wires 0-3, 4-7)
        const ulonglong2 vj1a = vv[2], vj1b = vv[3];   // w2 col of j+1

        #pragma unroll
        for (int t = 0; t < 2; t++) {
            // {s_j, s_{j+1}} in one packed chain — no horizontal add
            ull s = bp;
            s = ffma2(qd[t][0], u01.x, s);
            s = ffma2(qd[t][1], u01.y, s);
            s = ffma2(qd[t][2], u23.x, s);
            s = ffma2(qd[t][3], u23.y, s);
            s = ffma2(qd[t][4], u45.x, s);
            s = ffma2(qd[t][5], u45.y, s);
            s = ffma2(qd[t][6], u67.x, s);
            s = ffma2(qd[t][7], u67.y, s);
            float f0, f1; upk(s, f0, f1);
            f0 = fmaxf(f0, 0.f);
            f1 = fmaxf(f1, 0.f);
            const ull h0 = pk2(f0, f0);
            const ull h1 = pk2(f1, f1);
            acc[t][0] = ffma2(h0, vj0a.x, acc[t][0]);
            acc[t][1] = ffma2(h0, vj0a.y, acc[t][1]);
            acc[t][2] = ffma2(h0, vj0b.x, acc[t][2]);
            acc[t][3] = ffma2(h0, vj0b.y, acc[t][3]);
            acc[t][0] = ffma2(h1, vj1a.x, acc[t][0]);
            acc[t][1] = ffma2(h1, vj1a.y, acc[t][1]);
            acc[t][2] = ffma2(h1, vj1b.x, acc[t][2]);
            acc[t][3] = ffma2(h1, vj1b.y, acc[t][3]);
        }
    }

    float* base = g_part + (size_t)chunk * NTOK * DW;
    #pragma unroll
    for (int t = 0; t < 2; t++) {
        const int tok = tokA + t * FBLK;
        float o[8];
        #pragma unroll
        for (int wp = 0; wp < 4; wp++) upk(acc[t][wp], o[2*wp], o[2*wp+1]);
        *(float4*)(base + (size_t)tok * DW)     = make_float4(o[0], o[1], o[2], o[3]);
        *(float4*)(base + (size_t)tok * DW + 4) = make_float4(o[4], o[5], o[6], o[7]);
    }
}

// ============================================================
// Epilogue: reduce 8 partials + LN2 -> out
// ============================================================
__global__ __launch_bounds__(256)
void k_epilogue(const float* __restrict__ ln2_g, const float* __restrict__ ln2_b,
                const float* __restrict__ b2, float* __restrict__ out)
{
    const int tok = blockIdx.x * 256 + threadIdx.x;
    if (tok >= NTOK) return;

    float z[8];
    {
        const float4 ha = *(const float4*)(g_h + (size_t)tok * DW);
        const float4 hb = *(const float4*)(g_h + (size_t)tok * DW + 4);
        z[0]=ha.x; z[1]=ha.y; z[2]=ha.z; z[3]=ha.w;
        z[4]=hb.x; z[5]=hb.y; z[6]=hb.z; z[7]=hb.w;
    }
    #pragma unroll
    for (int c = 0; c < SPLIT; c++) {
        const float* p = g_part + (size_t)c * NTOK * DW + (size_t)tok * DW;
        const float4 pa = *(const float4*)(p);
        const float4 pb = *(const float4*)(p + 4);
        z[0]+=pa.x; z[1]+=pa.y; z[2]+=pa.z; z[3]+=pa.w;
        z[4]+=pb.x; z[5]+=pb.y; z[6]+=pb.z; z[7]+=pb.w;
    }
    float mu = 0.f;
    #pragma unroll
    for (int w = 0; w < 8; w++) { z[w] += __ldg(b2 + w); mu += z[w]; }
    mu *= 0.125f;
    float var = 0.f;
    #pragma unroll
    for (int w = 0; w < 8; w++) { float d = z[w] - mu; var += d * d; }
    var *= 0.125f;
    const float rs = rsqrtf(var + 1e-5f);
    float o[8];
    #pragma unroll
    for (int w = 0; w < 8; w++)
        o[w] = (z[w] - mu) * rs * __ldg(ln2_g + w) + __ldg(ln2_b + w);

    *(float4*)(out + (size_t)tok * DW)     = make_float4(o[0], o[1], o[2], o[3]);
    *(float4*)(out + (size_t)tok * DW + 4) = make_float4(o[4], o[5], o[6], o[7]);
}

// ============================================================
extern "C" void kernel_launch(void* const* d_in, const int* in_sizes, int n_in,
                              void* d_out, int out_size) {
    const float* x     = (const float*)d_in[0];
    const float* ln1_g = (const float*)d_in[1];
    const float* ln1_b = (const float*)d_in[2];
    const float* ln2_g = (const float*)d_in[3];
    const float* ln2_b = (const float*)d_in[4];
    const float* rp    = (const float*)d_in[5];
    const float* theta = (const float*)d_in[6];
    const float* w1    = (const float*)d_in[7];
    const float* b1    = (const float*)d_in[8];
    const float* w2    = (const float*)d_in[9];
    const float* b2    = (const float*)d_in[10];
    float* out = (float*)d_out;

    const int blocks = (NTOK / TPB) * SPLIT;   // 256 * 8 = 2048
    k_ffn<<<blocks, FBLK>>>(x, ln1_g, ln1_b, rp, theta, w1, b1, w2);
    k_epilogue<<<NTOK / 256, 256>>>(ln2_g, ln2_b, b2, out);
}

// round 5
// speedup vs baseline: 6.4106x; 2.5513x over previous
#include <cuda_runtime.h>
#include <cuda_fp16.h>

#define NTOK  131072
#define TPB   128          // threads per block == tokens per block
#define NGRP  64           // 64 groups of 16 FFN units

typedef unsigned int u32;

// pack two f32 -> f16x2, lo -> bits[15:0]
__device__ __forceinline__ u32 pkh(float lo, float hi) {
    u32 r; asm("cvt.rn.f16x2.f32 %0, %1, %2;" : "=r"(r) : "f"(hi), "f"(lo)); return r;
}
__device__ __forceinline__ u32 s2u(const void* p) {
    u32 a; asm("{.reg .u64 t; cvta.to.shared.u64 t, %1; cvt.u32.u64 %0, t;}" : "=r"(a) : "l"(p)); return a;
}
__device__ __forceinline__ void ldmat4(u32& a0, u32& a1, u32& a2, u32& a3, u32 addr) {
    asm volatile("ldmatrix.sync.aligned.m8n8.x4.shared.b16 {%0,%1,%2,%3}, [%4];"
                 : "=r"(a0), "=r"(a1), "=r"(a2), "=r"(a3) : "r"(addr));
}
__device__ __forceinline__ void mma16816(float* d, u32 a0, u32 a1, u32 a2, u32 a3,
                                         u32 b0, u32 b1, const float* c) {
    asm volatile("mma.sync.aligned.m16n8k16.row.col.f32.f16.f16.f32 "
                 "{%0,%1,%2,%3}, {%4,%5,%6,%7}, {%8,%9}, {%10,%11,%12,%13};"
                 : "=f"(d[0]), "=f"(d[1]), "=f"(d[2]), "=f"(d[3])
                 : "r"(a0), "r"(a1), "r"(a2), "r"(a3), "r"(b0), "r"(b1),
                   "f"(c[0]), "f"(c[1]), "f"(c[2]), "f"(c[3]));
}

__global__ __launch_bounds__(TPB)
void qtb_mma(const float* __restrict__ x,
             const float* __restrict__ ln1_g, const float* __restrict__ ln1_b,
             const float* __restrict__ ln2_g, const float* __restrict__ ln2_b,
             const float* __restrict__ rp,    const float* __restrict__ theta,
             const float* __restrict__ w1,    const float* __restrict__ b1,
             const float* __restrict__ w2,    const float* __restrict__ b2,
             float* __restrict__ out)
{
    // B fragments in exact mma layout. Per group m (units j=16m..16m+15), lane l
    // (g=l>>2, t=l&3):
    //  sw1g[m*32+l] = { f16x2{w1[16m+g][2t],   w1[16m+g][2t+1]},     (tile n=16m..+7)
    //                   f16x2{w1[16m+8+g][2t], w1[16m+8+g][2t+1]} }  (tile n=16m+8..+15)
    //  sw2g[m*32+l] = { f16x2{w2[g][16m+2t],   w2[g][16m+2t+1]},     (b0: k=2t,2t+1)
    //                   f16x2{w2[g][16m+8+2t], w2[g][16m+8+2t+1]} }  (b1: k=2t+8,2t+9)
    __shared__ uint2 sw1g[NGRP * 32];   // 16 KB
    __shared__ uint2 sw2g[NGRP * 32];   // 16 KB
    __shared__ float sb1[1024];         // 4 KB
    __shared__ uint4 sq[TPB * 2];       // 4 KB : per token 32B = [qhi x8 | qlo x8]
    __shared__ float sh[TPB * 8];       // 4 KB : LN1 output per token

    const int tid  = threadIdx.x;
    const int wid  = tid >> 5;
    const int lane = tid & 31;
    const int g    = lane >> 2;
    const int t    = lane & 3;

    // ---------- build weight fragments ----------
    for (int s = tid; s < NGRP * 32; s += TPB) {
        int m = s >> 5, l = s & 31;
        int gg = l >> 2, tt = l & 3;
        const float2 wa = *(const float2*)(w1 + (size_t)(16 * m + gg) * 8 + 2 * tt);
        const float2 wb = *(const float2*)(w1 + (size_t)(16 * m + 8 + gg) * 8 + 2 * tt);
        sw1g[s] = make_uint2(pkh(wa.x, wa.y), pkh(wb.x, wb.y));
        const float2 va = *(const float2*)(w2 + (size_t)gg * 1024 + 16 * m + 2 * tt);
        const float2 vb = *(const float2*)(w2 + (size_t)gg * 1024 + 16 * m + 8 + 2 * tt);
        sw2g[s] = make_uint2(pkh(va.x, va.y), pkh(vb.x, vb.y));
    }
    for (int s = tid; s < 1024; s += TPB) sb1[s] = b1[s];

    // ---------- prologue: one token per thread ----------
    const int tok = blockIdx.x * TPB + tid;
    {
        const float4 xa = __ldg((const float4*)(x + (size_t)tok * 8));
        const float4 xb = __ldg((const float4*)(x + (size_t)tok * 8 + 4));
        float xv[8] = {xa.x, xa.y, xa.z, xa.w, xb.x, xb.y, xb.z, xb.w};
        const float p0 = __ldg(rp+0), p1 = __ldg(rp+1), p3 = __ldg(rp+3), p4 = __ldg(rp+4);

        float a[8];
        float c0 = __cosf(xv[0] + p0);
        float c2 = __cosf(xv[2]);
        a[0] = c0;
        a[1] = c0 * __cosf(p1) * __cosf(xv[1]);
        a[2] = c2;
        a[3] = c2 * __cosf(xv[3]);
        a[4] = __cosf(xv[4] + p3);
        a[5] = __cosf(p4) * __cosf(xv[5]);
        a[6] = __cosf(xv[6]);
        a[7] = __cosf(xv[7]);

        // h = LN1(x + a) -> smem
        float y[8], mu = 0.f;
        #pragma unroll
        for (int w = 0; w < 8; w++) { y[w] = xv[w] + a[w]; mu += y[w]; }
        mu *= 0.125f;
        float var = 0.f;
        #pragma unroll
        for (int w = 0; w < 8; w++) { float d = y[w] - mu; var += d * d; }
        var *= 0.125f;
        float rs = rsqrtf(var + 1e-5f);
        #pragma unroll
        for (int w = 0; w < 8; w++)
            sh[tid * 8 + w] = (y[w] - mu) * rs * __ldg(ln1_g + w) + __ldg(ln1_b + w);

        // q split into fp16 hi/lo, packed row [hi x8 | lo x8]
        float q[8], bk[8];
        #pragma unroll
        for (int w = 0; w < 8; w++) {
            q[w] = __cosf(__ldg(theta + w)) * __cosf(a[w]);
            bk[w] = __half2float(__float2half_rn(q[w]));
        }
        sq[tid * 2 + 0] = make_uint4(pkh(q[0], q[1]), pkh(q[2], q[3]),
                                     pkh(q[4], q[5]), pkh(q[6], q[7]));
        sq[tid * 2 + 1] = make_uint4(pkh(q[0]-bk[0], q[1]-bk[1]), pkh(q[2]-bk[2], q[3]-bk[3]),
                                     pkh(q[4]-bk[4], q[5]-bk[5]), pkh(q[6]-bk[6], q[7]-bk[7]));
    }
    __syncthreads();

    // ---------- A fragments via ldmatrix (32 tokens per warp = 2 m16 tiles) ----------
    u32 a0, a1, a2, a3, e0, e1, e2, e3;
    {
        int r, off;
        if (lane < 16)      { r = lane;            off = 0;  }
        else if (lane < 24) { r = (lane & 7);      off = 16; }
        else                { r = (lane & 7) + 8;  off = 16; }
        u32 base = s2u(sq) + (u32)(wid * 32) * 32;
        ldmat4(a0, a1, a2, a3, base + (u32)r * 32 + off);          // tokens 0-15
        ldmat4(e0, e1, e2, e3, base + 512 + (u32)r * 32 + off);    // tokens 16-31
    }

    float acc0[4] = {0.f, 0.f, 0.f, 0.f};
    float acc1[4] = {0.f, 0.f, 0.f, 0.f};

    // ---------- main loop: 64 groups of 16 units ----------
    #pragma unroll 4
    for (int m = 0; m < NGRP; m++) {
        const uint2 wf = sw1g[m * 32 + lane];
        const float2 cb0 = *(const float2*)(sb1 + 16 * m + 2 * t);
        const float2 cb1 = *(const float2*)(sb1 + 16 * m + 8 + 2 * t);
        const float ci0[4] = {cb0.x, cb0.y, cb0.x, cb0.y};
        const float ci1[4] = {cb1.x, cb1.y, cb1.x, cb1.y};

        float d00[4], d01[4], d10[4], d11[4];
        mma16816(d00, a0, a1, a2, a3, wf.x, wf.x, ci0);   // tokens 0-15, units 16m..+7
        mma16816(d01, a0, a1, a2, a3, wf.y, wf.y, ci1);   // tokens 0-15, units +8..+15
        mma16816(d10, e0, e1, e2, e3, wf.x, wf.x, ci0);   // tokens 16-31
        mma16816(d11, e0, e1, e2, e3, wf.y, wf.y, ci1);

        // relu + f16 pack: D fragments become the A fragment of GEMM2 (k16 = 16 units)
        u32 f0 = pkh(fmaxf(d00[0], 0.f), fmaxf(d00[1], 0.f));
        u32 f1 = pkh(fmaxf(d00[2], 0.f), fmaxf(d00[3], 0.f));
        u32 f2 = pkh(fmaxf(d01[0], 0.f), fmaxf(d01[1], 0.f));
        u32 f3 = pkh(fmaxf(d01[2], 0.f), fmaxf(d01[3], 0.f));
        u32 h0 = pkh(fmaxf(d10[0], 0.f), fmaxf(d10[1], 0.f));
        u32 h1 = pkh(fmaxf(d10[2], 0.f), fmaxf(d10[3], 0.f));
        u32 h2 = pkh(fmaxf(d11[0], 0.f), fmaxf(d11[1], 0.f));
        u32 h3 = pkh(fmaxf(d11[2], 0.f), fmaxf(d11[3], 0.f));

        const uint2 w2f = sw2g[m * 32 + lane];
        mma16816(acc0, f0, f1, f2, f3, w2f.x, w2f.y, acc0);   // += H(0-15) @ W2^T
        mma16816(acc1, h0, h1, h2, h3, w2f.x, w2f.y, acc1);   // += H(16-31) @ W2^T
    }

    // ---------- epilogue: z = h + ffn + b2 -> LN2 -> out ----------
    {
        const int tb = blockIdx.x * TPB + wid * 32;
        const float2 bb = *(const float2*)(b2 + 2 * t);
        const float2 gg = *(const float2*)(ln2_g + 2 * t);
        const float2 bl = *(const float2*)(ln2_b + 2 * t);

        const int   rows[4] = {g, g + 8, g + 16, g + 24};
        const float zp[4][2] = {{acc0[0], acc0[1]}, {acc0[2], acc0[3]},
                                {acc1[0], acc1[1]}, {acc1[2], acc1[3]}};
        #pragma unroll
        for (int k = 0; k < 4; k++) {
            const int r = rows[k];
            const float2 hh = *(const float2*)(sh + (wid * 32 + r) * 8 + 2 * t);
            float z0 = hh.x + zp[k][0] + bb.x;
            float z1 = hh.y + zp[k][1] + bb.y;
            float s  = z0 + z1;
            float ss = z0 * z0 + z1 * z1;
            s  += __shfl_xor_sync(0xffffffffu, s, 1);
            s  += __shfl_xor_sync(0xffffffffu, s, 2);
            ss += __shfl_xor_sync(0xffffffffu, ss, 1);
            ss += __shfl_xor_sync(0xffffffffu, ss, 2);
            const float mu  = s * 0.125f;
            const float var = ss * 0.125f - mu * mu;
            const float rs  = rsqrtf(var + 1e-5f);
            const float o0 = (z0 - mu) * rs * gg.x + bl.x;
            const float o1 = (z1 - mu) * rs * gg.y + bl.y;
            *(float2*)(out + (size_t)(tb + r) * 8 + 2 * t) = make_float2(o0, o1);
        }
    }
}

// ============================================================
extern "C" void kernel_launch(void* const* d_in, const int* in_sizes, int n_in,
                              void* d_out, int out_size) {
    const float* x     = (const float*)d_in[0];
    const float* ln1_g = (const float*)d_in[1];
    const float* ln1_b = (const float*)d_in[2];
    const float* ln2_g = (const float*)d_in[3];
    const float* ln2_b = (const float*)d_in[4];
    const float* rp    = (const float*)d_in[5];
    const float* theta = (const float*)d_in[6];
    const float* w1    = (const float*)d_in[7];
    const float* b1    = (const float*)d_in[8];
    const float* w2    = (const float*)d_in[9];
    const float* b2    = (const float*)d_in[10];
    float* out = (float*)d_out;

    qtb_mma<<<NTOK / TPB, TPB>>>(x, ln1_g, ln1_b, ln2_g, ln2_b,
                                 rp, theta, w1, b1, w2, b2, out);
}

// round 8
// speedup vs baseline: 7.5996x; 1.1855x over previous
#include <cuda_runtime.h>
#include <cuda_fp16.h>

#define NTOK  131072
#define TPB   256          // threads per block == tokens per block
#define NGRP  64           // 64 groups of 16 FFN units

typedef unsigned int u32;

// pack two f32 -> f16x2, lo -> bits[15:0]
__device__ __forceinline__ u32 pkh(float lo, float hi) {
    u32 r; asm("cvt.rn.f16x2.f32 %0, %1, %2;" : "=r"(r) : "f"(hi), "f"(lo)); return r;
}
__device__ __forceinline__ u32 hmax2z(u32 a) {   // packed relu: max.f16x2(a, 0)
    u32 r; asm("max.f16x2 %0, %1, %2;" : "=r"(r) : "r"(a), "r"(0u)); return r;
}
__device__ __forceinline__ u32 s2u(const void* p) {
    u32 a; asm("{.reg .u64 t; cvta.to.shared.u64 t, %1; cvt.u32.u64 %0, t;}" : "=r"(a) : "l"(p)); return a;
}
__device__ __forceinline__ void ldmat4(u32& a0, u32& a1, u32& a2, u32& a3, u32 addr) {
    asm volatile("ldmatrix.sync.aligned.m8n8.x4.shared.b16 {%0,%1,%2,%3}, [%4];"
                 : "=r"(a0), "=r"(a1), "=r"(a2), "=r"(a3) : "r"(addr));
}
__device__ __forceinline__ void mma16816(float* d, u32 a0, u32 a1, u32 a2, u32 a3,
                                         u32 b0, u32 b1, const float* c) {
    asm volatile("mma.sync.aligned.m16n8k16.row.col.f32.f16.f16.f32 "
                 "{%0,%1,%2,%3}, {%4,%5,%6,%7}, {%8,%9}, {%10,%11,%12,%13};"
                 : "=f"(d[0]), "=f"(d[1]), "=f"(d[2]), "=f"(d[3])
                 : "r"(a0), "r"(a1), "r"(a2), "r"(a3), "r"(b0), "r"(b1),
                   "f"(c[0]), "f"(c[1]), "f"(c[2]), "f"(c[3]));
}

__global__ __launch_bounds__(TPB, 4)
void qtb_mma(const float* __restrict__ x,
             const float* __restrict__ ln1_g, const float* __restrict__ ln1_b,
             const float* __restrict__ ln2_g, const float* __restrict__ ln2_b,
             const float* __restrict__ rp,    const float* __restrict__ theta,
             const float* __restrict__ w1,    const float* __restrict__ b1,
             const float* __restrict__ w2,    const float* __restrict__ b2,
             float* __restrict__ out)
{
    // Weight fragments in exact mma layout. Per group m (units j=16m..16m+15),
    // lane l (g=l>>2, t=l&3):
    //  sw1g[m*32+l] = { f16x2{w1[16m+g][2t],   w1[16m+g][2t+1]},     (tile n=16m..+7)
    //                   f16x2{w1[16m+8+g][2t], w1[16m+8+g][2t+1]} }  (tile n=16m+8..+15)
    //  sw2g[m*32+l] = { f16x2{w2[g][16m+2t],   w2[g][16m+2t+1]},     (b0: k=2t,2t+1)
    //                   f16x2{w2[g][16m+8+2t], w2[g][16m+8+2t+1]} }  (b1: k=2t+8,2t+9)
    __shared__ uint2 sw1g[NGRP * 32];          // 16 KB
    __shared__ uint2 sw2g[NGRP * 32];          // 16 KB
    __shared__ float sb1[1024];                //  4 KB
    // Overlapped buffer: first holds q hi/lo rows (ldmatrix staging, 32B/token),
    // then (after each warp's ldmatrix) the same warp's slice is overwritten
    // with h (8 floats/token). Per-warp-private 1KB slices -> no cross-warp hazard.
    __shared__ __align__(16) char sqh[TPB * 32];   // 8 KB   (total 44 KB)

    const int tid  = threadIdx.x;
    const int wid  = tid >> 5;
    const int lane = tid & 31;
    const int g    = lane >> 2;
    const int t    = lane & 3;

    // ---------- build weight fragments ----------
    for (int s = tid; s < NGRP * 32; s += TPB) {
        int m = s >> 5, l = s & 31;
        int gg = l >> 2, tt = l & 3;
        const float2 wa = *(const float2*)(w1 + (size_t)(16 * m + gg) * 8 + 2 * tt);
        const float2 wb = *(const float2*)(w1 + (size_t)(16 * m + 8 + gg) * 8 + 2 * tt);
        sw1g[s] = make_uint2(pkh(wa.x, wa.y), pkh(wb.x, wb.y));
        const float2 va = *(const float2*)(w2 + (size_t)gg * 1024 + 16 * m + 2 * tt);
        const float2 vb = *(const float2*)(w2 + (size_t)gg * 1024 + 16 * m + 8 + 2 * tt);
        sw2g[s] = make_uint2(pkh(va.x, va.y), pkh(vb.x, vb.y));
    }
    for (int s = tid; s < 1024; s += TPB) sb1[s] = b1[s];

    // ---------- prologue: one token per thread; h kept in regs for now ----------
    const int tok = blockIdx.x * TPB + tid;
    float h[8];
    {
        const float4 xa = __ldg((const float4*)(x + (size_t)tok * 8));
        const float4 xb = __ldg((const float4*)(x + (size_t)tok * 8 + 4));
        float xv[8] = {xa.x, xa.y, xa.z, xa.w, xb.x, xb.y, xb.z, xb.w};
        const float p0 = __ldg(rp+0), p1 = __ldg(rp+1), p3 = __ldg(rp+3), p4 = __ldg(rp+4);

        float a[8];
        float c0 = __cosf(xv[0] + p0);
        float c2 = __cosf(xv[2]);
        a[0] = c0;
        a[1] = c0 * __cosf(p1) * __cosf(xv[1]);
        a[2] = c2;
        a[3] = c2 * __cosf(xv[3]);
        a[4] = __cosf(xv[4] + p3);
        a[5] = __cosf(p4) * __cosf(xv[5]);
        a[6] = __cosf(xv[6]);
        a[7] = __cosf(xv[7]);

        float y[8], mu = 0.f;
        #pragma unroll
        for (int w = 0; w < 8; w++) { y[w] = xv[w] + a[w]; mu += y[w]; }
        mu *= 0.125f;
        float var = 0.f;
        #pragma unroll
        for (int w = 0; w < 8; w++) { float d = y[w] - mu; var += d * d; }
        var *= 0.125f;
        float rs = rsqrtf(var + 1e-5f);
        #pragma unroll
        for (int w = 0; w < 8; w++)
            h[w] = (y[w] - mu) * rs * __ldg(ln1_g + w) + __ldg(ln1_b + w);

        // q split into fp16 hi/lo, packed row [hi x8 | lo x8]
        float q[8], bk[8];
        #pragma unroll
        for (int w = 0; w < 8; w++) {
            q[w] = __cosf(__ldg(theta + w)) * __cosf(a[w]);
            bk[w] = __half2float(__float2half_rn(q[w]));
        }
        uint4* sq = (uint4*)sqh;
        sq[tid * 2 + 0] = make_uint4(pkh(q[0], q[1]), pkh(q[2], q[3]),
                                     pkh(q[4], q[5]), pkh(q[6], q[7]));
        sq[tid * 2 + 1] = make_uint4(pkh(q[0]-bk[0], q[1]-bk[1]), pkh(q[2]-bk[2], q[3]-bk[3]),
                                     pkh(q[4]-bk[4], q[5]-bk[5]), pkh(q[6]-bk[6], q[7]-bk[7]));
    }
    __syncthreads();

    // ---------- A fragments via ldmatrix (32 tokens per warp = 2 m16 tiles) ----------
    u32 a0, a1, a2, a3, e0, e1, e2, e3;
    {
        int r, off;
        if (lane < 16)      { r = lane;            off = 0;  }
        else if (lane < 24) { r = (lane & 7);      off = 16; }
        else                { r = (lane & 7) + 8;  off = 16; }
        u32 base = s2u(sqh) + (u32)(wid * 32) * 32;
        ldmat4(a0, a1, a2, a3, base + (u32)r * 32 + off);          // tokens 0-15
        ldmat4(e0, e1, e2, e3, base + 512 + (u32)r * 32 + off);    // tokens 16-31
    }
    // ldmatrix is warp-synchronous; this warp's sq slice is now dead — overwrite with h.
    {
        float* shv = (float*)sqh;
        #pragma unroll
        for (int w = 0; w < 8; w++) shv[tid * 8 + w] = h[w];
    }

    float acc0[4] = {0.f, 0.f, 0.f, 0.f};
    float acc1[4] = {0.f, 0.f, 0.f, 0.f};

    // ---------- main loop: 64 groups of 16 units ----------
    #pragma unroll 4
    for (int m = 0; m < NGRP; m++) {
        const uint2 wf = sw1g[m * 32 + lane];
        const float2 cb0 = *(const float2*)(sb1 + 16 * m + 2 * t);
        const float2 cb1 = *(const float2*)(sb1 + 16 * m + 8 + 2 * t);
        const float ci0[4] = {cb0.x, cb0.y, cb0.x, cb0.y};
        const float ci1[4] = {cb1.x, cb1.y, cb1.x, cb1.y};

        float d00[4], d01[4], d10[4], d11[4];
        mma16816(d00, a0, a1, a2, a3, wf.x, wf.x, ci0);   // tokens 0-15, units 16m..+7
        mma16816(d01, a0, a1, a2, a3, wf.y, wf.y, ci1);   // tokens 0-15, units +8..+15
        mma16816(d10, e0, e1, e2, e3, wf.x, wf.x, ci0);   // tokens 16-31
        mma16816(d11, e0, e1, e2, e3, wf.y, wf.y, ci1);

        // cvt then packed relu: D fragments -> A fragment of GEMM2
        u32 f0 = hmax2z(pkh(d00[0], d00[1]));
        u32 f1 = hmax2z(pkh(d00[2], d00[3]));
        u32 f2 = hmax2z(pkh(d01[0], d01[1]));
        u32 f3 = hmax2z(pkh(d01[2], d01[3]));
        u32 h0 = hmax2z(pkh(d10[0], d10[1]));
        u32 h1 = hmax2z(pkh(d10[2], d10[3]));
        u32 h2 = hmax2z(pkh(d11[0], d11[1]));
        u32 h3 = hmax2z(pkh(d11[2], d11[3]));

        const uint2 w2f = sw2g[m * 32 + lane];
        mma16816(acc0, f0, f1, f2, f3, w2f.x, w2f.y, acc0);   // += H(0-15) @ W2^T
        mma16816(acc1, h0, h1, h2, h3, w2f.x, w2f.y, acc1);   // += H(16-31) @ W2^T
    }

    // ---------- epilogue: z = h + ffn + b2 -> LN2 -> out ----------
    {
        const int tb = blockIdx.x * TPB + wid * 32;
        const float2 bb = *(const float2*)(b2 + 2 * t);
        const float2 gg = *(const float2*)(ln2_g + 2 * t);
        const float2 bl = *(const float2*)(ln2_b + 2 * t);
        const float* shv = (const float*)sqh;

        const int   rows[4] = {g, g + 8, g + 16, g + 24};
        const float zp[4][2] = {{acc0[0], acc0[1]}, {acc0[2], acc0[3]},
                                {acc1[0], acc1[1]}, {acc1[2], acc1[3]}};
        #pragma unroll
        for (int k = 0; k < 4; k++) {
            const int r = rows[k];
            const float2 hh = *(const float2*)(shv + (wid * 32 + r) * 8 + 2 * t);
            float z0 = hh.x + zp[k][0] + bb.x;
            float z1 = hh.y + zp[k][1] + bb.y;
            float s  = z0 + z1;
            float ss = z0 * z0 + z1 * z1;
            s  += __shfl_xor_sync(0xffffffffu, s, 1);
            s  += __shfl_xor_sync(0xffffffffu, s, 2);
            ss += __shfl_xor_sync(0xffffffffu, ss, 1);
            ss += __shfl_xor_sync(0xffffffffu, ss, 2);
            const float mu  = s * 0.125f;
            const float var = ss * 0.125f - mu * mu;
            const float rs  = rsqrtf(var + 1e-5f);
            const float o0 = (z0 - mu) * rs * gg.x + bl.x;
            const float o1 = (z1 - mu) * rs * gg.y + bl.y;
            *(float2*)(out + (size_t)(tb + r) * 8 + 2 * t) = make_float2(o0, o1);
        }
    }
}

// ============================================================
extern "C" void kernel_launch(void* const* d_in, const int* in_sizes, int n_in,
                              void* d_out, int out_size) {
    const float* x     = (const float*)d_in[0];
    const float* ln1_g = (const float*)d_in[1];
    const float* ln1_b = (const float*)d_in[2];
    const float* ln2_g = (const float*)d_in[3];
    const float* ln2_b = (const float*)d_in[4];
    const float* rp    = (const float*)d_in[5];
    const float* theta = (const float*)d_in[6];
    const float* w1    = (const float*)d_in[7];
    const float* b1    = (const float*)d_in[8];
    const float* w2    = (const float*)d_in[9];
    const float* b2    = (const float*)d_in[10];
    float* out = (float*)d_out;

    qtb_mma<<<NTOK / TPB, TPB>>>(x, ln1_g, ln1_b, ln2_g, ln2_b,
                                 rp, theta, w1, b1, w2, b2, out);
}

// round 10
// speedup vs baseline: 8.1688x; 1.0749x over previous
#include <cuda_runtime.h>
#include <cuda_fp16.h>

#define NTOK  131072
#define TPB   256          // threads per block == tokens per block
#define NGRP  64           // 64 groups of 16 FFN units

typedef unsigned int u32;

// pack two f32 -> f16x2, lo -> bits[15:0]
__device__ __forceinline__ u32 pkh(float lo, float hi) {
    u32 r; asm("cvt.rn.f16x2.f32 %0, %1, %2;" : "=r"(r) : "f"(hi), "f"(lo)); return r;
}
__device__ __forceinline__ u32 hmax2z(u32 a) {   // packed relu: max.f16x2(a, 0)
    u32 r; asm("max.f16x2 %0, %1, %2;" : "=r"(r) : "r"(a), "r"(0u)); return r;
}
__device__ __forceinline__ u32 s2u(const void* p) {
    u32 a; asm("{.reg .u64 t; cvta.to.shared.u64 t, %1; cvt.u32.u64 %0, t;}" : "=r"(a) : "l"(p)); return a;
}
__device__ __forceinline__ void ldmat4(u32& a0, u32& a1, u32& a2, u32& a3, u32 addr) {
    asm volatile("ldmatrix.sync.aligned.m8n8.x4.shared.b16 {%0,%1,%2,%3}, [%4];"
                 : "=r"(a0), "=r"(a1), "=r"(a2), "=r"(a3) : "r"(addr));
}
// GEMM1: m16n8k8 (A = q fp16, 2 regs)
__device__ __forceinline__ void mma16808(float* d, u32 a0, u32 a1, u32 b0, const float* c) {
    asm volatile("mma.sync.aligned.m16n8k8.row.col.f32.f16.f16.f32 "
                 "{%0,%1,%2,%3}, {%4,%5}, {%6}, {%7,%8,%9,%10};"
                 : "=f"(d[0]), "=f"(d[1]), "=f"(d[2]), "=f"(d[3])
                 : "r"(a0), "r"(a1), "r"(b0),
                   "f"(c[0]), "f"(c[1]), "f"(c[2]), "f"(c[3]));
}
// GEMM2: m16n8k16
__device__ __forceinline__ void mma16816(float* d, u32 a0, u32 a1, u32 a2, u32 a3,
                                         u32 b0, u32 b1, const float* c) {
    asm volatile("mma.sync.aligned.m16n8k16.row.col.f32.f16.f16.f32 "
                 "{%0,%1,%2,%3}, {%4,%5,%6,%7}, {%8,%9}, {%10,%11,%12,%13};"
                 : "=f"(d[0]), "=f"(d[1]), "=f"(d[2]), "=f"(d[3])
                 : "r"(a0), "r"(a1), "r"(a2), "r"(a3), "r"(b0), "r"(b1),
                   "f"(c[0]), "f"(c[1]), "f"(c[2]), "f"(c[3]));
}

__global__ __launch_bounds__(TPB, 4)
void qtb_mma(const float* __restrict__ x,
             const float* __restrict__ ln1_g, const float* __restrict__ ln1_b,
             const float* __restrict__ ln2_g, const float* __restrict__ ln2_b,
             const float* __restrict__ rp,    const float* __restrict__ theta,
             const float* __restrict__ w1,    const float* __restrict__ b1,
             const float* __restrict__ w2,    const float* __restrict__ b2,
             float* __restrict__ out)
{
    // Weight fragments in exact mma layout (lane l: g=l>>2, t=l&3):
    //  sw1g[m*32+l] = { f16x2{w1[16m+g][2t], w1[16m+g][2t+1]},      (B frag units 16m..+7)
    //                   f16x2{w1[16m+8+g][2t], w1[16m+8+g][2t+1]} } (units 16m+8..+15)
    //  sw2g[m*32+l] = { f16x2{w2[g][16m+2t],   w2[g][16m+2t+1]},
    //                   f16x2{w2[g][16m+8+2t], w2[g][16m+8+2t+1]} }
    __shared__ uint2 sw1g[NGRP * 32];          // 16 KB
    __shared__ uint2 sw2g[NGRP * 32];          // 16 KB
    __shared__ float sb1[1024];                //  4 KB
    // ldmatrix staging: 32B/token rows; q fp16 in first 16B. After each warp's
    // ldmatrix, the warp's own slice is reused for h (8 floats/token).
    __shared__ __align__(16) char sqh[TPB * 32];   // 8 KB   (total 44 KB)

    const int tid  = threadIdx.x;
    const int wid  = tid >> 5;
    const int lane = tid & 31;
    const int g    = lane >> 2;
    const int t    = lane & 3;

    // ---------- build weight fragments ----------
    for (int s = tid; s < NGRP * 32; s += TPB) {
        int m = s >> 5, l = s & 31;
        int gg = l >> 2, tt = l & 3;
        const float2 wa = *(const float2*)(w1 + (size_t)(16 * m + gg) * 8 + 2 * tt);
        const float2 wb = *(const float2*)(w1 + (size_t)(16 * m + 8 + gg) * 8 + 2 * tt);
        sw1g[s] = make_uint2(pkh(wa.x, wa.y), pkh(wb.x, wb.y));
        const float2 va = *(const float2*)(w2 + (size_t)gg * 1024 + 16 * m + 2 * tt);
        const float2 vb = *(const float2*)(w2 + (size_t)gg * 1024 + 16 * m + 8 + 2 * tt);
        sw2g[s] = make_uint2(pkh(va.x, va.y), pkh(vb.x, vb.y));
    }
    for (int s = tid; s < 1024; s += TPB) sb1[s] = b1[s];

    // ---------- prologue: one token per thread ----------
    const int tok = blockIdx.x * TPB + tid;
    float h[8];
    {
        const float4 xa = __ldg((const float4*)(x + (size_t)tok * 8));
        const float4 xb = __ldg((const float4*)(x + (size_t)tok * 8 + 4));
        float xv[8] = {xa.x, xa.y, xa.z, xa.w, xb.x, xb.y, xb.z, xb.w};
        const float p0 = __ldg(rp+0), p1 = __ldg(rp+1), p3 = __ldg(rp+3), p4 = __ldg(rp+4);

        float a[8];
        float c0 = __cosf(xv[0] + p0);
        float c2 = __cosf(xv[2]);
        a[0] = c0;
        a[1] = c0 * __cosf(p1) * __cosf(xv[1]);
        a[2] = c2;
        a[3] = c2 * __cosf(xv[3]);
        a[4] = __cosf(xv[4] + p3);
        a[5] = __cosf(p4) * __cosf(xv[5]);
        a[6] = __cosf(xv[6]);
        a[7] = __cosf(xv[7]);

        float y[8], mu = 0.f;
        #pragma unroll
        for (int w = 0; w < 8; w++) { y[w] = xv[w] + a[w]; mu += y[w]; }
        mu *= 0.125f;
        float var = 0.f;
        #pragma unroll
        for (int w = 0; w < 8; w++) { float d = y[w] - mu; var += d * d; }
        var *= 0.125f;
        float rs = rsqrtf(var + 1e-5f);
        #pragma unroll
        for (int w = 0; w < 8; w++)
            h[w] = (y[w] - mu) * rs * __ldg(ln1_g + w) + __ldg(ln1_b + w);

        // q in plain fp16 (hi only) packed into the first 16B of the 32B row
        float q[8];
        #pragma unroll
        for (int w = 0; w < 8; w++) q[w] = __cosf(__ldg(theta + w)) * __cosf(a[w]);
        *(uint4*)(sqh + tid * 32) = make_uint4(pkh(q[0], q[1]), pkh(q[2], q[3]),
                                               pkh(q[4], q[5]), pkh(q[6], q[7]));
    }
    __syncthreads();

    // ---------- A fragments: ONE ldmatrix.x4 covers both m16 token tiles ----------
    // matrix0/1 = tokens 0-15 (a0,a1), matrix2/3 = tokens 16-31 (e0,e1); row = lane.
    u32 a0, a1, e0, e1;
    {
        u32 base = s2u(sqh) + (u32)(wid * 32) * 32;
        ldmat4(a0, a1, e0, e1, base + (u32)lane * 32);
    }
    // warp-synchronous: this warp's staging slice is dead — overwrite with h
    {
        float* shv = (float*)sqh;
        #pragma unroll
        for (int w = 0; w < 8; w++) shv[tid * 8 + w] = h[w];
    }

    // 4 independent GEMM2 accumulator chains (even m / odd m), merged at the end
    float accA0[4] = {0,0,0,0}, accA1[4] = {0,0,0,0};   // even m: tokens 0-15 / 16-31
    float accB0[4] = {0,0,0,0}, accB1[4] = {0,0,0,0};   // odd  m

    #pragma unroll 2
    for (int m = 0; m < NGRP; m += 2) {
        // ---- even iteration (chains A) ----
        {
            const uint2 wf = sw1g[m * 32 + lane];
            const float2 cb0 = *(const float2*)(sb1 + 16 * m + 2 * t);
            const float2 cb1 = *(const float2*)(sb1 + 16 * m + 8 + 2 * t);
            const float ci0[4] = {cb0.x, cb0.y, cb0.x, cb0.y};
            const float ci1[4] = {cb1.x, cb1.y, cb1.x, cb1.y};

            float d00[4], d01[4], d10[4], d11[4];
            mma16808(d00, a0, a1, wf.x, ci0);
            mma16808(d01, a0, a1, wf.y, ci1);
            mma16808(d10, e0, e1, wf.x, ci0);
            mma16808(d11, e0, e1, wf.y, ci1);

            u32 f0 = hmax2z(pkh(d00[0], d00[1]));
            u32 f1 = hmax2z(pkh(d00[2], d00[3]));
            u32 f2 = hmax2z(pkh(d01[0], d01[1]));
            u32 f3 = hmax2z(pkh(d01[2], d01[3]));
            u32 h0 = hmax2z(pkh(d10[0], d10[1]));
            u32 h1 = hmax2z(pkh(d10[2], d10[3]));
            u32 h2 = hmax2z(pkh(d11[0], d11[1]));
            u32 h3 = hmax2z(pkh(d11[2], d11[3]));

            const uint2 w2f = sw2g[m * 32 + lane];
            mma16816(accA0, f0, f1, f2, f3, w2f.x, w2f.y, accA0);
            mma16816(accA1, h0, h1, h2, h3, w2f.x, w2f.y, accA1);
        }
        // ---- odd iteration (chains B) ----
        {
            const int mo = m + 1;
            const uint2 wf = sw1g[mo * 32 + lane];
            const float2 cb0 = *(const float2*)(sb1 + 16 * mo + 2 * t);
            const float2 cb1 = *(const float2*)(sb1 + 16 * mo + 8 + 2 * t);
            const float ci0[4] = {cb0.x, cb0.y, cb0.x, cb0.y};
            const float ci1[4] = {cb1.x, cb1.y, cb1.x, cb1.y};

            float d00[4], d01[4], d10[4], d11[4];
            mma16808(d00, a0, a1, wf.x, ci0);
            mma16808(d01, a0, a1, wf.y, ci1);
            mma16808(d10, e0, e1, wf.x, ci0);
            mma16808(d11, e0, e1, wf.y, ci1);

            u32 f0 = hmax2z(pkh(d00[0], d00[1]));
            u32 f1 = hmax2z(pkh(d00[2], d00[3]));
            u32 f2 = hmax2z(pkh(d01[0], d01[1]));
            u32 f3 = hmax2z(pkh(d01[2], d01[3]));
            u32 h0 = hmax2z(pkh(d10[0], d10[1]));
            u32 h1 = hmax2z(pkh(d10[2], d10[3]));
            u32 h2 = hmax2z(pkh(d11[0], d11[1]));
            u32 h3 = hmax2z(pkh(d11[2], d11[3]));

            const uint2 w2f = sw2g[mo * 32 + lane];
            mma16816(accB0, f0, f1, f2, f3, w2f.x, w2f.y, accB0);
            mma16816(accB1, h0, h1, h2, h3, w2f.x, w2f.y, accB1);
        }
    }

    // merge chains
    float acc0[4], acc1[4];
    #pragma unroll
    for (int k = 0; k < 4; k++) { acc0[k] = accA0[k] + accB0[k]; acc1[k] = accA1[k] + accB1[k]; }

    // ---------- epilogue: z = h + ffn + b2 -> LN2 -> out ----------
    {
        const int tb = blockIdx.x * TPB + wid * 32;
        const float2 bb = *(const float2*)(b2 + 2 * t);
        const float2 gg = *(const float2*)(ln2_g + 2 * t);
        const float2 bl = *(const float2*)(ln2_b + 2 * t);
        const float* shv = (const float*)sqh;

        const int   rows[4] = {g, g + 8, g + 16, g + 24};
        const float zp[4][2] = {{acc0[0], acc0[1]}, {acc0[2], acc0[3]},
                                {acc1[0], acc1[1]}, {acc1[2], acc1[3]}};
        #pragma unroll
        for (int k = 0; k < 4; k++) {
            const int r = rows[k];
            const float2 hh = *(const float2*)(shv + (wid * 32 + r) * 8 + 2 * t);
            float z0 = hh.x + zp[k][0] + bb.x;
            float z1 = hh.y + zp[k][1] + bb.y;
            float s  = z0 + z1;
            float ss = z0 * z0 + z1 * z1;
            s  += __shfl_xor_sync(0xffffffffu, s, 1);
            s  += __shfl_xor_sync(0xffffffffu, s, 2);
            ss += __shfl_xor_sync(0xffffffffu, ss, 1);
            ss += __shfl_xor_sync(0xffffffffu, ss, 2);
            const float mu  = s * 0.125f;
            const float var = ss * 0.125f - mu * mu;
            const float rs  = rsqrtf(var + 1e-5f);
            const float o0 = (z0 - mu) * rs * gg.x + bl.x;
            const float o1 = (z1 - mu) * rs * gg.y + bl.y;
            *(float2*)(out + (size_t)(tb + r) * 8 + 2 * t) = make_float2(o0, o1);
        }
    }
}

// ============================================================
extern "C" void kernel_launch(void* const* d_in, const int* in_sizes, int n_in,
                              void* d_out, int out_size) {
    const float* x     = (const float*)d_in[0];
    const float* ln1_g = (const float*)d_in[1];
    const float* ln1_b = (const float*)d_in[2];
    const float* ln2_g = (const float*)d_in[3];
    const float* ln2_b = (const float*)d_in[4];
    const float* rp    = (const float*)d_in[5];
    const float* theta = (const float*)d_in[6];
    const float* w1    = (const float*)d_in[7];
    const float* b1    = (const float*)d_in[8];
    const float* w2    = (const float*)d_in[9];
    const float* b2    = (const float*)d_in[10];
    float* out = (float*)d_out;

    qtb_mma<<<NTOK / TPB, TPB>>>(x, ln1_g, ln1_b, ln2_g, ln2_b,
                                 rp, theta, w1, b1, w2, b2, out);
}

// round 11
// speedup vs baseline: 8.4357x; 1.0327x over previous
#include <cuda_runtime.h>
#include <cuda_fp16.h>

#define NTOK  131072
#define TPB   256          // threads per block == tokens per block
#define NGRP  64           // 64 groups of 16 FFN units

// dynamic smem layout (bytes)
#define OFF_W1   0                       // uint4[NGRP*32]  : 32 KB (w1 + bias packed)
#define OFF_W2   32768                   // uint2[NGRP*32]  : 16 KB
#define OFF_QH   49152                   // char[TPB*32]    :  8 KB (staging, then h)
#define SMEM_DYN 57344                   // 56 KB

typedef unsigned int u32;

// pack two f32 -> f16x2, lo -> bits[15:0]
__device__ __forceinline__ u32 pkh(float lo, float hi) {
    u32 r; asm("cvt.rn.f16x2.f32 %0, %1, %2;" : "=r"(r) : "f"(hi), "f"(lo)); return r;
}
__device__ __forceinline__ u32 hmax2z(u32 a) {   // packed relu: max.f16x2(a, 0)
    u32 r; asm("max.f16x2 %0, %1, %2;" : "=r"(r) : "r"(a), "r"(0u)); return r;
}
__device__ __forceinline__ u32 s2u(const void* p) {
    u32 a; asm("{.reg .u64 t; cvta.to.shared.u64 t, %1; cvt.u32.u64 %0, t;}" : "=r"(a) : "l"(p)); return a;
}
__device__ __forceinline__ void ldmat4(u32& a0, u32& a1, u32& a2, u32& a3, u32 addr) {
    asm volatile("ldmatrix.sync.aligned.m8n8.x4.shared.b16 {%0,%1,%2,%3}, [%4];"
                 : "=r"(a0), "=r"(a1), "=r"(a2), "=r"(a3) : "r"(addr));
}
// m16n8k16, f16 in / f32 acc
__device__ __forceinline__ void mma16816(float* d, u32 a0, u32 a1, u32 a2, u32 a3,
                                         u32 b0, u32 b1, const float* c) {
    asm volatile("mma.sync.aligned.m16n8k16.row.col.f32.f16.f16.f32 "
                 "{%0,%1,%2,%3}, {%4,%5,%6,%7}, {%8,%9}, {%10,%11,%12,%13};"
                 : "=f"(d[0]), "=f"(d[1]), "=f"(d[2]), "=f"(d[3])
                 : "r"(a0), "r"(a1), "r"(a2), "r"(a3), "r"(b0), "r"(b1),
                   "f"(c[0]), "f"(c[1]), "f"(c[2]), "f"(c[3]));
}

__global__ __launch_bounds__(TPB, 4)
void qtb_mma(const float* __restrict__ x,
             const float* __restrict__ ln1_g, const float* __restrict__ ln1_b,
             const float* __restrict__ ln2_g, const float* __restrict__ ln2_b,
             const float* __restrict__ rp,    const float* __restrict__ theta,
             const float* __restrict__ w1,    const float* __restrict__ b1,
             const float* __restrict__ w2,    const float* __restrict__ b2,
             float* __restrict__ out)
{
    extern __shared__ __align__(16) char smem[];
    uint4* sw1g = (uint4*)(smem + OFF_W1);   // per (m,lane): {B0_t0, Bb_t0, B0_t1, Bb_t1}
    uint2* sw2g = (uint2*)(smem + OFF_W2);
    char*  sqh  = smem + OFF_QH;

    const int tid  = threadIdx.x;
    const int wid  = tid >> 5;
    const int lane = tid & 31;
    const int g    = lane >> 2;
    const int t    = lane & 3;

    // ---------- build weight fragments ----------
    // GEMM1 B-frag (m16n8k16, col-major B, col g, lane t):
    //   reg b0 = f16x2{ w1[n][2t], w1[n][2t+1] }        (k = 0..7: real wires)
    //   reg b1 = (t==0) ? f16x2{ b1[n], 0 } : 0          (k = 8..15: bias lane; A has 1.0 at k=8)
    for (int s = tid; s < NGRP * 32; s += TPB) {
        int m = s >> 5, l = s & 31;
        int gg = l >> 2, tt = l & 3;
        const int n0 = 16 * m + gg;
        const int n1 = n0 + 8;
        const float2 wa = *(const float2*)(w1 + (size_t)n0 * 8 + 2 * tt);
        const float2 wb = *(const float2*)(w1 + (size_t)n1 * 8 + 2 * tt);
        u32 bias0 = 0u, bias1 = 0u;
        if (tt == 0) {
            bias0 = pkh(__ldg(b1 + n0), 0.f);
            bias1 = pkh(__ldg(b1 + n1), 0.f);
        }
        sw1g[s] = make_uint4(pkh(wa.x, wa.y), bias0, pkh(wb.x, wb.y), bias1);
        const float2 va = *(const float2*)(w2 + (size_t)gg * 1024 + 16 * m + 2 * tt);
        const float2 vb = *(const float2*)(w2 + (size_t)gg * 1024 + 16 * m + 8 + 2 * tt);
        sw2g[s] = make_uint2(pkh(va.x, va.y), pkh(vb.x, vb.y));
    }

    // ---------- prologue: one token per thread ----------
    const int tok = blockIdx.x * TPB + tid;
    float h[8];
    {
        const float4 xa = __ldg((const float4*)(x + (size_t)tok * 8));
        const float4 xb = __ldg((const float4*)(x + (size_t)tok * 8 + 4));
        float xv[8] = {xa.x, xa.y, xa.z, xa.w, xb.x, xb.y, xb.z, xb.w};
        const float p0 = __ldg(rp+0), p1 = __ldg(rp+1), p3 = __ldg(rp+3), p4 = __ldg(rp+4);

        float a[8];
        float c0 = __cosf(xv[0] + p0);
        float c2 = __cosf(xv[2]);
        a[0] = c0;
        a[1] = c0 * __cosf(p1) * __cosf(xv[1]);
        a[2] = c2;
        a[3] = c2 * __cosf(xv[3]);
        a[4] = __cosf(xv[4] + p3);
        a[5] = __cosf(p4) * __cosf(xv[5]);
        a[6] = __cosf(xv[6]);
        a[7] = __cosf(xv[7]);

        float y[8], mu = 0.f;
        #pragma unroll
        for (int w = 0; w < 8; w++) { y[w] = xv[w] + a[w]; mu += y[w]; }
        mu *= 0.125f;
        float var = 0.f;
        #pragma unroll
        for (int w = 0; w < 8; w++) { float d = y[w] - mu; var += d * d; }
        var *= 0.125f;
        float rs = rsqrtf(var + 1e-5f);
        #pragma unroll
        for (int w = 0; w < 8; w++)
            h[w] = (y[w] - mu) * rs * __ldg(ln1_g + w) + __ldg(ln1_b + w);

        // q in fp16 packed into the first 16B of the 32B staging row
        float q[8];
        #pragma unroll
        for (int w = 0; w < 8; w++) q[w] = __cosf(__ldg(theta + w)) * __cosf(a[w]);
        *(uint4*)(sqh + tid * 32) = make_uint4(pkh(q[0], q[1]), pkh(q[2], q[3]),
                                               pkh(q[4], q[5]), pkh(q[6], q[7]));
    }
    __syncthreads();

    // ---------- A fragments: one ldmatrix.x4 covers both m16 token tiles ----------
    u32 a0, a1, e0, e1;
    {
        u32 base = s2u(sqh) + (u32)(wid * 32) * 32;
        ldmat4(a0, a1, e0, e1, base + (u32)lane * 32);
    }
    // constant upper-k A half: 1.0 at k=8 (t==0 lanes), 0 elsewhere
    const u32 c1 = (t == 0) ? 0x00003C00u : 0u;
    // warp-synchronous: staging slice dead — overwrite with h
    {
        float* shv = (float*)sqh;
        #pragma unroll
        for (int w = 0; w < 8; w++) shv[tid * 8 + w] = h[w];
    }

    const float z4[4] = {0.f, 0.f, 0.f, 0.f};

    // 4 independent GEMM2 accumulator chains (even m / odd m)
    float accA0[4] = {0,0,0,0}, accA1[4] = {0,0,0,0};
    float accB0[4] = {0,0,0,0}, accB1[4] = {0,0,0,0};

    #pragma unroll 2
    for (int m = 0; m < NGRP; m += 2) {
        // ---- even iteration (chains A) ----
        {
            const uint4 W = sw1g[m * 32 + lane];
            float d00[4], d01[4], d10[4], d11[4];
            mma16816(d00, a0, a1, c1, c1, W.x, W.y, z4);   // tokens 0-15, units 16m..+7
            mma16816(d01, a0, a1, c1, c1, W.z, W.w, z4);   // units 16m+8..+15
            mma16816(d10, e0, e1, c1, c1, W.x, W.y, z4);   // tokens 16-31
            mma16816(d11, e0, e1, c1, c1, W.z, W.w, z4);

            u32 f0 = hmax2z(pkh(d00[0], d00[1]));
            u32 f1 = hmax2z(pkh(d00[2], d00[3]));
            u32 f2 = hmax2z(pkh(d01[0], d01[1]));
            u32 f3 = hmax2z(pkh(d01[2], d01[3]));
            u32 h0 = hmax2z(pkh(d10[0], d10[1]));
            u32 h1 = hmax2z(pkh(d10[2], d10[3]));
            u32 h2 = hmax2z(pkh(d11[0], d11[1]));
            u32 h3 = hmax2z(pkh(d11[2], d11[3]));

            const uint2 V = sw2g[m * 32 + lane];
            mma16816(accA0, f0, f1, f2, f3, V.x, V.y, accA0);
            mma16816(accA1, h0, h1, h2, h3, V.x, V.y, accA1);
        }
        // ---- odd iteration (chains B) ----
        {
            const int mo = m + 1;
            const uint4 W = sw1g[mo * 32 + lane];
            float d00[4], d01[4], d10[4], d11[4];
            mma16816(d00, a0, a1, c1, c1, W.x, W.y, z4);
            mma16816(d01, a0, a1, c1, c1, W.z, W.w, z4);
            mma16816(d10, e0, e1, c1, c1, W.x, W.y, z4);
            mma16816(d11, e0, e1, c1, c1, W.z, W.w, z4);

            u32 f0 = hmax2z(pkh(d00[0], d00[1]));
            u32 f1 = hmax2z(pkh(d00[2], d00[3]));
            u32 f2 = hmax2z(pkh(d01[0], d01[1]));
            u32 f3 = hmax2z(pkh(d01[2], d01[3]));
            u32 h0 = hmax2z(pkh(d10[0], d10[1]));
            u32 h1 = hmax2z(pkh(d10[2], d10[3]));
            u32 h2 = hmax2z(pkh(d11[0], d11[1]));
            u32 h3 = hmax2z(pkh(d11[2], d11[3]));

            const uint2 V = sw2g[mo * 32 + lane];
            mma16816(accB0, f0, f1, f2, f3, V.x, V.y, accB0);
            mma16816(accB1, h0, h1, h2, h3, V.x, V.y, accB1);
        }
    }

    float acc0[4], acc1[4];
    #pragma unroll
    for (int k = 0; k < 4; k++) { acc0[k] = accA0[k] + accB0[k]; acc1[k] = accA1[k] + accB1[k]; }

    // ---------- epilogue: z = h + ffn + b2 -> LN2 -> out ----------
    {
        const int tb = blockIdx.x * TPB + wid * 32;
        const float2 bb = *(const float2*)(b2 + 2 * t);
        const float2 gg = *(const float2*)(ln2_g + 2 * t);
        const float2 bl = *(const float2*)(ln2_b + 2 * t);
        const float* shv = (const float*)sqh;

        const int   rows[4] = {g, g + 8, g + 16, g + 24};
        const float zp[4][2] = {{acc0[0], acc0[1]}, {acc0[2], acc0[3]},
                                {acc1[0], acc1[1]}, {acc1[2], acc1[3]}};
        #pragma unroll
        for (int k = 0; k < 4; k++) {
            const int r = rows[k];
            const float2 hh = *(const float2*)(shv + (wid * 32 + r) * 8 + 2 * t);
            float z0 = hh.x + zp[k][0] + bb.x;
            float z1 = hh.y + zp[k][1] + bb.y;
            float s  = z0 + z1;
            float ss = z0 * z0 + z1 * z1;
            s  += __shfl_xor_sync(0xffffffffu, s, 1);
            s  += __shfl_xor_sync(0xffffffffu, s, 2);
            ss += __shfl_xor_sync(0xffffffffu, ss, 1);
            ss += __shfl_xor_sync(0xffffffffu, ss, 2);
            const float mu  = s * 0.125f;
            const float var = ss * 0.125f - mu * mu;
            const float rs  = rsqrtf(var + 1e-5f);
            const float o0 = (z0 - mu) * rs * gg.x + bl.x;
            const float o1 = (z1 - mu) * rs * gg.y + bl.y;
            *(float2*)(out + (size_t)(tb + r) * 8 + 2 * t) = make_float2(o0, o1);
        }
    }
}

// ============================================================
extern "C" void kernel_launch(void* const* d_in, const int* in_sizes, int n_in,
                              void* d_out, int out_size) {
    const float* x     = (const float*)d_in[0];
    const float* ln1_g = (const float*)d_in[1];
    const float* ln1_b = (const float*)d_in[2];
    const float* ln2_g = (const float*)d_in[3];
    const float* ln2_b = (const float*)d_in[4];
    const float* rp    = (const float*)d_in[5];
    const float* theta = (const float*)d_in[6];
    const float* w1    = (const float*)d_in[7];
    const float* b1    = (const float*)d_in[8];
    const float* w2    = (const float*)d_in[9];
    const float* b2    = (const float*)d_in[10];
    float* out = (float*)d_out;

    cudaFuncSetAttribute(qtb_mma, cudaFuncAttributeMaxDynamicSharedMemorySize, SMEM_DYN);
    qtb_mma<<<NTOK / TPB, TPB, SMEM_DYN>>>(x, ln1_g, ln1_b, ln2_g, ln2_b,
                                           rp, theta, w1, b1, w2, b2, out);
}

// round 12
// speedup vs baseline: 8.6719x; 1.0280x over previous
#include <cuda_runtime.h>
#include <cuda_fp16.h>

#define NTOK  131072
#define TPB   256          // threads per block == tokens per block
#define NGRP  64           // 64 groups of 16 FFN units

// dynamic smem layout (bytes)
#define OFF_W1   0                       // uint4[NGRP*32]  : 32 KB (w1 + bias packed)
#define OFF_W2   32768                   // uint2[NGRP*32]  : 16 KB
#define OFF_QH   49152                   // char[TPB*32]    :  8 KB (staging, then h)
#define SMEM_DYN 57344                   // 56 KB

typedef unsigned int u32;

// pack two f32 -> f16x2, lo -> bits[15:0]
__device__ __forceinline__ u32 pkh(float lo, float hi) {
    u32 r; asm("cvt.rn.f16x2.f32 %0, %1, %2;" : "=r"(r) : "f"(hi), "f"(lo)); return r;
}
// fused pack + relu: cvt.rn.relu (sm_86+) clamps negatives to +0 during convert
__device__ __forceinline__ u32 pkhr(float lo, float hi) {
    u32 r; asm("cvt.rn.relu.f16x2.f32 %0, %1, %2;" : "=r"(r) : "f"(hi), "f"(lo)); return r;
}
__device__ __forceinline__ u32 s2u(const void* p) {
    u32 a; asm("{.reg .u64 t; cvta.to.shared.u64 t, %1; cvt.u32.u64 %0, t;}" : "=r"(a) : "l"(p)); return a;
}
__device__ __forceinline__ void ldmat4(u32& a0, u32& a1, u32& a2, u32& a3, u32 addr) {
    asm volatile("ldmatrix.sync.aligned.m8n8.x4.shared.b16 {%0,%1,%2,%3}, [%4];"
                 : "=r"(a0), "=r"(a1), "=r"(a2), "=r"(a3) : "r"(addr));
}
// m16n8k16, f16 in / f32 acc
__device__ __forceinline__ void mma16816(float* d, u32 a0, u32 a1, u32 a2, u32 a3,
                                         u32 b0, u32 b1, const float* c) {
    asm volatile("mma.sync.aligned.m16n8k16.row.col.f32.f16.f16.f32 "
                 "{%0,%1,%2,%3}, {%4,%5,%6,%7}, {%8,%9}, {%10,%11,%12,%13};"
                 : "=f"(d[0]), "=f"(d[1]), "=f"(d[2]), "=f"(d[3])
                 : "r"(a0), "r"(a1), "r"(a2), "r"(a3), "r"(b0), "r"(b1),
                   "f"(c[0]), "f"(c[1]), "f"(c[2]), "f"(c[3]));
}

__global__ __launch_bounds__(TPB, 4)
void qtb_mma(const float* __restrict__ x,
             const float* __restrict__ ln1_g, const float* __restrict__ ln1_b,
             const float* __restrict__ ln2_g, const float* __restrict__ ln2_b,
             const float* __restrict__ rp,    const float* __restrict__ theta,
             const float* __restrict__ w1,    const float* __restrict__ b1,
             const float* __restrict__ w2,    const float* __restrict__ b2,
             float* __restrict__ out)
{
    extern __shared__ __align__(16) char smem[];
    uint4* sw1g = (uint4*)(smem + OFF_W1);   // per (m,lane): {B0_t0, Bb_t0, B0_t1, Bb_t1}
    uint2* sw2g = (uint2*)(smem + OFF_W2);
    char*  sqh  = smem + OFF_QH;

    const int tid  = threadIdx.x;
    const int wid  = tid >> 5;
    const int lane = tid & 31;
    const int g    = lane >> 2;
    const int t    = lane & 3;

    // ---------- build weight fragments ----------
    // GEMM1 B-frag (m16n8k16, col-major B, col g, lane t):
    //   reg b0 = f16x2{ w1[n][2t], w1[n][2t+1] }        (k = 0..7: real wires)
    //   reg b1 = (t==0) ? f16x2{ b1[n], 0 } : 0          (k = 8..15: bias lane; A has 1.0 at k=8)
    for (int s = tid; s < NGRP * 32; s += TPB) {
        int m = s >> 5, l = s & 31;
        int gg = l >> 2, tt = l & 3;
        const int n0 = 16 * m + gg;
        const int n1 = n0 + 8;
        const float2 wa = *(const float2*)(w1 + (size_t)n0 * 8 + 2 * tt);
        const float2 wb = *(const float2*)(w1 + (size_t)n1 * 8 + 2 * tt);
        u32 bias0 = 0u, bias1 = 0u;
        if (tt == 0) {
            bias0 = pkh(__ldg(b1 + n0), 0.f);
            bias1 = pkh(__ldg(b1 + n1), 0.f);
        }
        sw1g[s] = make_uint4(pkh(wa.x, wa.y), bias0, pkh(wb.x, wb.y), bias1);
        const float2 va = *(const float2*)(w2 + (size_t)gg * 1024 + 16 * m + 2 * tt);
        const float2 vb = *(const float2*)(w2 + (size_t)gg * 1024 + 16 * m + 8 + 2 * tt);
        sw2g[s] = make_uint2(pkh(va.x, va.y), pkh(vb.x, vb.y));
    }

    // ---------- prologue: one token per thread ----------
    const int tok = blockIdx.x * TPB + tid;
    float h[8];
    {
        const float4 xa = __ldg((const float4*)(x + (size_t)tok * 8));
        const float4 xb = __ldg((const float4*)(x + (size_t)tok * 8 + 4));
        float xv[8] = {xa.x, xa.y, xa.z, xa.w, xb.x, xb.y, xb.z, xb.w};
        const float p0 = __ldg(rp+0), p1 = __ldg(rp+1), p3 = __ldg(rp+3), p4 = __ldg(rp+4);

        float a[8];
        float c0 = __cosf(xv[0] + p0);
        float c2 = __cosf(xv[2]);
        a[0] = c0;
        a[1] = c0 * __cosf(p1) * __cosf(xv[1]);
        a[2] = c2;
        a[3] = c2 * __cosf(xv[3]);
        a[4] = __cosf(xv[4] + p3);
        a[5] = __cosf(p4) * __cosf(xv[5]);
        a[6] = __cosf(xv[6]);
        a[7] = __cosf(xv[7]);

        float y[8], mu = 0.f;
        #pragma unroll
        for (int w = 0; w < 8; w++) { y[w] = xv[w] + a[w]; mu += y[w]; }
        mu *= 0.125f;
        float var = 0.f;
        #pragma unroll
        for (int w = 0; w < 8; w++) { float d = y[w] - mu; var += d * d; }
        var *= 0.125f;
        float rs = rsqrtf(var + 1e-5f);
        #pragma unroll
        for (int w = 0; w < 8; w++)
            h[w] = (y[w] - mu) * rs * __ldg(ln1_g + w) + __ldg(ln1_b + w);

        // q in fp16 packed into the first 16B of the 32B staging row
        float q[8];
        #pragma unroll
        for (int w = 0; w < 8; w++) q[w] = __cosf(__ldg(theta + w)) * __cosf(a[w]);
        *(uint4*)(sqh + tid * 32) = make_uint4(pkh(q[0], q[1]), pkh(q[2], q[3]),
                                               pkh(q[4], q[5]), pkh(q[6], q[7]));
    }
    __syncthreads();

    // ---------- A fragments: one ldmatrix.x4 covers both m16 token tiles ----------
    u32 a0, a1, e0, e1;
    {
        u32 base = s2u(sqh) + (u32)(wid * 32) * 32;
        ldmat4(a0, a1, e0, e1, base + (u32)lane * 32);
    }
    // constant upper-k A half: 1.0 at k=8 (t==0 lanes), 0 elsewhere
    const u32 c1 = (t == 0) ? 0x00003C00u : 0u;
    // warp-synchronous: staging slice dead — overwrite with h
    {
        float* shv = (float*)sqh;
        #pragma unroll
        for (int w = 0; w < 8; w++) shv[tid * 8 + w] = h[w];
    }

    const float z4[4] = {0.f, 0.f, 0.f, 0.f};

    // 4 independent GEMM2 accumulator chains (even m / odd m)
    float accA0[4] = {0,0,0,0}, accA1[4] = {0,0,0,0};
    float accB0[4] = {0,0,0,0}, accB1[4] = {0,0,0,0};

    #pragma unroll 4
    for (int m = 0; m < NGRP; m += 2) {
        // ---- even iteration (chains A) ----
        {
            const uint4 W = sw1g[m * 32 + lane];
            float d00[4], d01[4], d10[4], d11[4];
            mma16816(d00, a0, a1, c1, c1, W.x, W.y, z4);   // tokens 0-15, units 16m..+7
            mma16816(d01, a0, a1, c1, c1, W.z, W.w, z4);   // units 16m+8..+15
            mma16816(d10, e0, e1, c1, c1, W.x, W.y, z4);   // tokens 16-31
            mma16816(d11, e0, e1, c1, c1, W.z, W.w, z4);

            // fused cvt+relu: D fragments -> A fragment of GEMM2
            u32 f0 = pkhr(d00[0], d00[1]);
            u32 f1 = pkhr(d00[2], d00[3]);
            u32 f2 = pkhr(d01[0], d01[1]);
            u32 f3 = pkhr(d01[2], d01[3]);
            u32 h0 = pkhr(d10[0], d10[1]);
            u32 h1 = pkhr(d10[2], d10[3]);
            u32 h2 = pkhr(d11[0], d11[1]);
            u32 h3 = pkhr(d11[2], d11[3]);

            const uint2 V = sw2g[m * 32 + lane];
            mma16816(accA0, f0, f1, f2, f3, V.x, V.y, accA0);
            mma16816(accA1, h0, h1, h2, h3, V.x, V.y, accA1);
        }
        // ---- odd iteration (chains B) ----
        {
            const int mo = m + 1;
            const uint4 W = sw1g[mo * 32 + lane];
            float d00[4], d01[4], d10[4], d11[4];
            mma16816(d00, a0, a1, c1, c1, W.x, W.y, z4);
            mma16816(d01, a0, a1, c1, c1, W.z, W.w, z4);
            mma16816(d10, e0, e1, c1, c1, W.x, W.y, z4);
            mma16816(d11, e0, e1, c1, c1, W.z, W.w, z4);

            u32 f0 = pkhr(d00[0], d00[1]);
            u32 f1 = pkhr(d00[2], d00[3]);
            u32 f2 = pkhr(d01[0], d01[1]);
            u32 f3 = pkhr(d01[2], d01[3]);
            u32 h0 = pkhr(d10[0], d10[1]);
            u32 h1 = pkhr(d10[2], d10[3]);
            u32 h2 = pkhr(d11[0], d11[1]);
            u32 h3 = pkhr(d11[2], d11[3]);

            const uint2 V = sw2g[mo * 32 + lane];
            mma16816(accB0, f0, f1, f2, f3, V.x, V.y, accB0);
            mma16816(accB1, h0, h1, h2, h3, V.x, V.y, accB1);
        }
    }

    float acc0[4], acc1[4];
    #pragma unroll
    for (int k = 0; k < 4; k++) { acc0[k] = accA0[k] + accB0[k]; acc1[k] = accA1[k] + accB1[k]; }

    // ---------- epilogue: z = h + ffn + b2 -> LN2 -> out ----------
    {
        const int tb = blockIdx.x * TPB + wid * 32;
        const float2 bb = *(const float2*)(b2 + 2 * t);
        const float2 gg = *(const float2*)(ln2_g + 2 * t);
        const float2 bl = *(const float2*)(ln2_b + 2 * t);
        const float* shv = (const float*)sqh;

        const int   rows[4] = {g, g + 8, g + 16, g + 24};
        const float zp[4][2] = {{acc0[0], acc0[1]}, {acc0[2], acc0[3]},
                                {acc1[0], acc1[1]}, {acc1[2], acc1[3]}};
        #pragma unroll
        for (int k = 0; k < 4; k++) {
            const int r = rows[k];
            const float2 hh = *(const float2*)(shv + (wid * 32 + r) * 8 + 2 * t);
            float z0 = hh.x + zp[k][0] + bb.x;
            float z1 = hh.y + zp[k][1] + bb.y;
            float s  = z0 + z1;
            float ss = z0 * z0 + z1 * z1;
            s  += __shfl_xor_sync(0xffffffffu, s, 1);
            s  += __shfl_xor_sync(0xffffffffu, s, 2);
            ss += __shfl_xor_sync(0xffffffffu, ss, 1);
            ss += __shfl_xor_sync(0xffffffffu, ss, 2);
            const float mu  = s * 0.125f;
            const float var = ss * 0.125f - mu * mu;
            const float rs  = rsqrtf(var + 1e-5f);
            const float o0 = (z0 - mu) * rs * gg.x + bl.x;
            const float o1 = (z1 - mu) * rs * gg.y + bl.y;
            *(float2*)(out + (size_t)(tb + r) * 8 + 2 * t) = make_float2(o0, o1);
        }
    }
}

// ============================================================
extern "C" void kernel_launch(void* const* d_in, const int* in_sizes, int n_in,
                              void* d_out, int out_size) {
    const float* x     = (const float*)d_in[0];
    const float* ln1_g = (const float*)d_in[1];
    const float* ln1_b = (const float*)d_in[2];
    const float* ln2_g = (const float*)d_in[3];
    const float* ln2_b = (const float*)d_in[4];
    const float* rp    = (const float*)d_in[5];
    const float* theta = (const float*)d_in[6];
    const float* w1    = (const float*)d_in[7];
    const float* b1    = (const float*)d_in[8];
    const float* w2    = (const float*)d_in[9];
    const float* b2    = (const float*)d_in[10];
    float* out = (float*)d_out;

    cudaFuncSetAttribute(qtb_mma, cudaFuncAttributeMaxDynamicSharedMemorySize, SMEM_DYN);
    qtb_mma<<<NTOK / TPB, TPB, SMEM_DYN>>>(x, ln1_g, ln1_b, ln2_g, ln2_b,
                                           rp, theta, w1, b1, w2, b2, out);
}

// round 15
// speedup vs baseline: 10.0965x; 1.1643x over previous
#include <cuda_runtime.h>
#include <cuda_fp16.h>

#define NTOK  131072
#define TPB   128          // tokens per block == threads per block
#define NGRP  64           // 64 groups of 16 FFN units

typedef unsigned int u32;

// Precomputed weight fragment tables (built once by k_setup; L1-resident)
__device__ uint4 g_w1f[NGRP * 32];   // 32 KB : GEMM1 B-frags + bias lane
__device__ uint2 g_w2f[NGRP * 32];   // 16 KB : GEMM2 B-frags

// pack two f32 -> f16x2, lo -> bits[15:0]
__device__ __forceinline__ u32 pkh(float lo, float hi) {
    u32 r; asm("cvt.rn.f16x2.f32 %0, %1, %2;" : "=r"(r) : "f"(hi), "f"(lo)); return r;
}
// fused pack + relu (sm_86+)
__device__ __forceinline__ u32 pkhr(float lo, float hi) {
    u32 r; asm("cvt.rn.relu.f16x2.f32 %0, %1, %2;" : "=r"(r) : "f"(hi), "f"(lo)); return r;
}
__device__ __forceinline__ u32 s2u(const void* p) {
    u32 a; asm("{.reg .u64 t; cvta.to.shared.u64 t, %1; cvt.u32.u64 %0, t;}" : "=r"(a) : "l"(p)); return a;
}
__device__ __forceinline__ void ldmat4(u32& a0, u32& a1, u32& a2, u32& a3, u32 addr) {
    asm volatile("ldmatrix.sync.aligned.m8n8.x4.shared.b16 {%0,%1,%2,%3}, [%4];"
                 : "=r"(a0), "=r"(a1), "=r"(a2), "=r"(a3) : "r"(addr));
}
__device__ __forceinline__ void mma16816(float* d, u32 a0, u32 a1, u32 a2, u32 a3,
                                         u32 b0, u32 b1, const float* c) {
    asm volatile("mma.sync.aligned.m16n8k16.row.col.f32.f16.f16.f32 "
                 "{%0,%1,%2,%3}, {%4,%5,%6,%7}, {%8,%9}, {%10,%11,%12,%13};"
                 : "=f"(d[0]), "=f"(d[1]), "=f"(d[2]), "=f"(d[3])
                 : "r"(a0), "r"(a1), "r"(a2), "r"(a3), "r"(b0), "r"(b1),
                   "f"(c[0]), "f"(c[1]), "f"(c[2]), "f"(c[3]));
}

// ============================================================
// Setup: build fragment tables once (2048 frag sets)
// ============================================================
__global__ __launch_bounds__(256)
void k_setup(const float* __restrict__ w1, const float* __restrict__ b1,
             const float* __restrict__ w2)
{
    const int s = blockIdx.x * 256 + threadIdx.x;    // 0..2047
    const int m  = s >> 5, l = s & 31;
    const int gg = l >> 2, tt = l & 3;
    const int n0 = 16 * m + gg;
    const int n1 = n0 + 8;
    // GEMM1 B-frag (col-major B, col gg, lane tt):
    //   b0 = f16x2{ w1[n][2t], w1[n][2t+1] }  (k=0..7 real wires)
    //   b1 = (t==0) ? f16x2{ b1[n], 0 } : 0   (k=8..15 bias lane; A has 1.0 at k=8)
    const float2 wa = *(const float2*)(w1 + (size_t)n0 * 8 + 2 * tt);
    const float2 wb = *(const float2*)(w1 + (size_t)n1 * 8 + 2 * tt);
    u32 bias0 = 0u, bias1 = 0u;
    if (tt == 0) {
        bias0 = pkh(__ldg(b1 + n0), 0.f);
        bias1 = pkh(__ldg(b1 + n1), 0.f);
    }
    g_w1f[s] = make_uint4(pkh(wa.x, wa.y), bias0, pkh(wb.x, wb.y), bias1);
    const float2 va = *(const float2*)(w2 + (size_t)gg * 1024 + 16 * m + 2 * tt);
    const float2 vb = *(const float2*)(w2 + (size_t)gg * 1024 + 16 * m + 8 + 2 * tt);
    g_w2f[s] = make_uint2(pkh(va.x, va.y), pkh(vb.x, vb.y));
}

// ============================================================
// Main kernel: 128 tokens/CTA, 8 CTA/SM, weights via L1
// ============================================================
__global__ __launch_bounds__(TPB, 8)
void qtb_mma(const float* __restrict__ x,
             const float* __restrict__ ln1_g, const float* __restrict__ ln1_b,
             const float* __restrict__ ln2_g, const float* __restrict__ ln2_b,
             const float* __restrict__ rp,    const float* __restrict__ theta,
             const float* __restrict__ b2,    float* __restrict__ out)
{
    // ldmatrix staging (32B/token rows, q fp16 in first 16B), then reused for h.
    // All accesses are warp-private (each warp touches only its 32 tokens).
    __shared__ __align__(16) char sqh[TPB * 32];   // 4 KB

    const int tid  = threadIdx.x;
    const int wid  = tid >> 5;
    const int lane = tid & 31;
    const int g    = lane >> 2;
    const int t    = lane & 3;

    // ---------- prologue: one token per thread ----------
    const int tok = blockIdx.x * TPB + tid;
    float h[8];
    {
        const float4 xa = __ldg((const float4*)(x + (size_t)tok * 8));
        const float4 xb = __ldg((const float4*)(x + (size_t)tok * 8 + 4));
        float xv[8] = {xa.x, xa.y, xa.z, xa.w, xb.x, xb.y, xb.z, xb.w};
        const float p0 = __ldg(rp+0), p1 = __ldg(rp+1), p3 = __ldg(rp+3), p4 = __ldg(rp+4);

        float a[8];
        float c0 = __cosf(xv[0] + p0);
        float c2 = __cosf(xv[2]);
        a[0] = c0;
        a[1] = c0 * __cosf(p1) * __cosf(xv[1]);
        a[2] = c2;
        a[3] = c2 * __cosf(xv[3]);
        a[4] = __cosf(xv[4] + p3);
        a[5] = __cosf(p4) * __cosf(xv[5]);
        a[6] = __cosf(xv[6]);
        a[7] = __cosf(xv[7]);

        float y[8], mu = 0.f;
        #pragma unroll
        for (int w = 0; w < 8; w++) { y[w] = xv[w] + a[w]; mu += y[w]; }
        mu *= 0.125f;
        float var = 0.f;
        #pragma unroll
        for (int w = 0; w < 8; w++) { float d = y[w] - mu; var += d * d; }
        var *= 0.125f;
        float rs = rsqrtf(var + 1e-5f);
        #pragma unroll
        for (int w = 0; w < 8; w++)
            h[w] = (y[w] - mu) * rs * __ldg(ln1_g + w) + __ldg(ln1_b + w);

        float q[8];
        #pragma unroll
        for (int w = 0; w < 8; w++) q[w] = __cosf(__ldg(theta + w)) * __cosf(a[w]);
        *(uint4*)(sqh + tid * 32) = make_uint4(pkh(q[0], q[1]), pkh(q[2], q[3]),
                                               pkh(q[4], q[5]), pkh(q[6], q[7]));
    }
    __syncwarp();   // order staging writes before ldmatrix (warp-private data)

    // ---------- A fragments: one ldmatrix.x4 covers both m16 token tiles ----------
    u32 a0, a1, e0, e1;
    {
        u32 base = s2u(sqh) + (u32)(wid * 32) * 32;
        ldmat4(a0, a1, e0, e1, base + (u32)lane * 32);
    }
    const u32 c1 = (t == 0) ? 0x00003C00u : 0u;   // A upper-k: 1.0 at k=8
    __syncwarp();
    {
        float* shv = (float*)sqh;                 // staging dead -> store h
        #pragma unroll
        for (int w = 0; w < 8; w++) shv[tid * 8 + w] = h[w];
    }

    const float z4[4] = {0.f, 0.f, 0.f, 0.f};

    // 4 independent GEMM2 accumulator chains (even m / odd m)
    float accA0[4] = {0,0,0,0}, accA1[4] = {0,0,0,0};
    float accB0[4] = {0,0,0,0}, accB1[4] = {0,0,0,0};

    #pragma unroll 4
    for (int m = 0; m < NGRP; m += 2) {
        // ---- even iteration (chains A) ----
        {
            const uint4 W = __ldg(&g_w1f[m * 32 + lane]);
            float d00[4], d01[4], d10[4], d11[4];
            mma16816(d00, a0, a1, c1, c1, W.x, W.y, z4);   // tokens 0-15, units 16m..+7
            mma16816(d01, a0, a1, c1, c1, W.z, W.w, z4);   // units 16m+8..+15
            mma16816(d10, e0, e1, c1, c1, W.x, W.y, z4);   // tokens 16-31
            mma16816(d11, e0, e1, c1, c1, W.z, W.w, z4);

            u32 f0 = pkhr(d00[0], d00[1]);
            u32 f1 = pkhr(d00[2], d00[3]);
            u32 f2 = pkhr(d01[0], d01[1]);
            u32 f3 = pkhr(d01[2], d01[3]);
            u32 h0 = pkhr(d10[0], d10[1]);
            u32 h1 = pkhr(d10[2], d10[3]);
            u32 h2 = pkhr(d11[0], d11[1]);
            u32 h3 = pkhr(d11[2], d11[3]);

            const uint2 V = __ldg(&g_w2f[m * 32 + lane]);
            mma16816(accA0, f0, f1, f2, f3, V.x, V.y, accA0);
            mma16816(accA1, h0, h1, h2, h3, V.x, V.y, accA1);
        }
        // ---- odd iteration (chains B) ----
        {
            const int mo = m + 1;
            const uint4 W = __ldg(&g_w1f[mo * 32 + lane]);
            float d00[4], d01[4], d10[4], d11[4];
            mma16816(d00, a0, a1, c1, c1, W.x, W.y, z4);
            mma16816(d01, a0, a1, c1, c1, W.z, W.w, z4);
            mma16816(d10, e0, e1, c1, c1, W.x, W.y, z4);
            mma16816(d11, e0, e1, c1, c1, W.z, W.w, z4);

            u32 f0 = pkhr(d00[0], d00[1]);
            u32 f1 = pkhr(d00[2], d00[3]);
            u32 f2 = pkhr(d01[0], d01[1]);
            u32 f3 = pkhr(d01[2], d01[3]);
            u32 h0 = pkhr(d10[0], d10[1]);
            u32 h1 = pkhr(d10[2], d10[3]);
            u32 h2 = pkhr(d11[0], d11[1]);
            u32 h3 = pkhr(d11[2], d11[3]);

            const uint2 V = __ldg(&g_w2f[mo * 32 + lane]);
            mma16816(accB0, f0, f1, f2, f3, V.x, V.y, accB0);
            mma16816(accB1, h0, h1, h2, h3, V.x, V.y, accB1);
        }
    }

    float acc0[4], acc1[4];
    #pragma unroll
    for (int k = 0; k < 4; k++) { acc0[k] = accA0[k] + accB0[k]; acc1[k] = accA1[k] + accB1[k]; }

    // ---------- epilogue: z = h + ffn + b2 -> LN2 -> out ----------
    {
        const int tb = blockIdx.x * TPB + wid * 32;
        const float2 bb = *(const float2*)(b2 + 2 * t);
        const float2 gg = *(const float2*)(ln2_g + 2 * t);
        const float2 bl = *(const float2*)(ln2_b + 2 * t);
        const float* shv = (const float*)sqh;

        const int   rows[4] = {g, g + 8, g + 16, g + 24};
        const float zp[4][2] = {{acc0[0], acc0[1]}, {acc0[2], acc0[3]},
                                {acc1[0], acc1[1]}, {acc1[2], acc1[3]}};
        #pragma unroll
        for (int k = 0; k < 4; k++) {
            const int r = rows[k];
            const float2 hh = *(const float2*)(shv + (wid * 32 + r) * 8 + 2 * t);
            float z0 = hh.x + zp[k][0] + bb.x;
            float z1 = hh.y + zp[k][1] + bb.y;
            float s  = z0 + z1;
            float ss = z0 * z0 + z1 * z1;
            s  += __shfl_xor_sync(0xffffffffu, s, 1);
            s  += __shfl_xor_sync(0xffffffffu, s, 2);
            ss += __shfl_xor_sync(0xffffffffu, ss, 1);
            ss += __shfl_xor_sync(0xffffffffu, ss, 2);
            const float mu  = s * 0.125f;
            const float var = ss * 0.125f - mu * mu;
            const float rs  = rsqrtf(var + 1e-5f);
            const float o0 = (z0 - mu) * rs * gg.x + bl.x;
            const float o1 = (z1 - mu) * rs * gg.y + bl.y;
            *(float2*)(out + (size_t)(tb + r) * 8 + 2 * t) = make_float2(o0, o1);
        }
    }
}

// ============================================================
extern "C" void kernel_launch(void* const* d_in, const int* in_sizes, int n_in,
                              void* d_out, int out_size) {
    const float* x     = (const float*)d_in[0];
    const float* ln1_g = (const float*)d_in[1];
    const float* ln1_b = (const float*)d_in[2];
    const float* ln2_g = (const float*)d_in[3];
    const float* ln2_b = (const float*)d_in[4];
    const float* rp    = (const float*)d_in[5];
    const float* theta = (const float*)d_in[6];
    const float* w1    = (const float*)d_in[7];
    const float* b1    = (const float*)d_in[8];
    const float* w2    = (const float*)d_in[9];
    const float* b2    = (const float*)d_in[10];
    float* out = (float*)d_out;

    k_setup<<<8, 256>>>(w1, b1, w2);
    qtb_mma<<<NTOK / TPB, TPB>>>(x, ln1_g, ln1_b, ln2_g, ln2_b,
                                 rp, theta, b2, out);
}